// round 1
// baseline (speedup 1.0000x reference)
#include <cuda_runtime.h>
#include <math.h>

#define NN    8192
#define FIN   256
#define FOUT  128
#define TI    16          // attention rows per block
#define THETA 25.0f       // softmax truncation threshold (in e-units)
#define SLOPE 0.01f       // leaky relu negative slope

// -------- scratch (device globals; no allocation allowed) --------
__device__ float g_Xp[NN * FOUT];     // 4 MB, fp32 projected features
__device__ float g_asrc[NN];
__device__ float g_adst[NN];
__device__ float g_maxadst[1];

// ===================================================================
// Kernel 1: Xp = X @ W^T + b     (X: [NN,FIN], W: [FOUT,FIN] row-major)
// 64x64 tile, 16x16 threads, 4x4 per thread, K-tile 16
// ===================================================================
__global__ void gemm_xp_kernel(const float* __restrict__ X,
                               const float* __restrict__ W,
                               const float* __restrict__ b) {
    __shared__ float Xs[64][17];
    __shared__ float Ws[64][17];
    const int tx = threadIdx.x, ty = threadIdx.y;
    const int tid = ty * 16 + tx;
    const int row0 = blockIdx.y * 64;
    const int col0 = blockIdx.x * 64;

    const int lr = tid >> 2;          // 0..63
    const int lk = (tid & 3) * 4;     // 0,4,8,12

    float acc[4][4];
#pragma unroll
    for (int i = 0; i < 4; i++)
#pragma unroll
        for (int j = 0; j < 4; j++) acc[i][j] = 0.f;

    for (int kt = 0; kt < FIN; kt += 16) {
        float4 xv = *reinterpret_cast<const float4*>(&X[(row0 + lr) * FIN + kt + lk]);
        Xs[lr][lk + 0] = xv.x; Xs[lr][lk + 1] = xv.y;
        Xs[lr][lk + 2] = xv.z; Xs[lr][lk + 3] = xv.w;
        float4 wv = *reinterpret_cast<const float4*>(&W[(col0 + lr) * FIN + kt + lk]);
        Ws[lr][lk + 0] = wv.x; Ws[lr][lk + 1] = wv.y;
        Ws[lr][lk + 2] = wv.z; Ws[lr][lk + 3] = wv.w;
        __syncthreads();
#pragma unroll
        for (int k = 0; k < 16; ++k) {
            float a[4], w[4];
#pragma unroll
            for (int i = 0; i < 4; i++) a[i] = Xs[ty * 4 + i][k];
#pragma unroll
            for (int j = 0; j < 4; j++) w[j] = Ws[tx * 4 + j][k];
#pragma unroll
            for (int i = 0; i < 4; i++)
#pragma unroll
                for (int j = 0; j < 4; j++) acc[i][j] += a[i] * w[j];
        }
        __syncthreads();
    }
#pragma unroll
    for (int i = 0; i < 4; i++) {
#pragma unroll
        for (int j = 0; j < 4; j++) {
            int f = col0 + tx * 4 + j;
            g_Xp[(row0 + ty * 4 + i) * FOUT + f] = acc[i][j] + b[f];
        }
    }
}

// ===================================================================
// Kernel 2: a_src[i] = Xp[i,:]·S[:128],  a_dst[i] = Xp[i,:]·S[128:]
// one warp per row, float4 loads
// ===================================================================
__global__ void proj_kernel(const float* __restrict__ S) {
    int gw   = (blockIdx.x * blockDim.x + threadIdx.x) >> 5;
    int lane = threadIdx.x & 31;
    if (gw >= NN) return;
    const float4 x  = *((const float4*)(g_Xp + gw * FOUT) + lane);
    const float4 s1 = *((const float4*)(S) + lane);
    const float4 s2 = *((const float4*)(S + FOUT) + lane);
    float ss = x.x * s1.x + x.y * s1.y + x.z * s1.z + x.w * s1.w;
    float sd = x.x * s2.x + x.y * s2.y + x.z * s2.z + x.w * s2.w;
#pragma unroll
    for (int o = 16; o > 0; o >>= 1) {
        ss += __shfl_down_sync(0xffffffffu, ss, o);
        sd += __shfl_down_sync(0xffffffffu, sd, o);
    }
    if (lane == 0) { g_asrc[gw] = ss; g_adst[gw] = sd; }
}

// ===================================================================
// Kernel 3: global max of a_dst (single block; fresh write each launch)
// ===================================================================
__global__ void maxred_kernel() {
    __shared__ float red[32];
    int t = threadIdx.x;  // 1024
    float m = -1e30f;
    for (int i = t; i < NN; i += 1024) m = fmaxf(m, g_adst[i]);
#pragma unroll
    for (int o = 16; o > 0; o >>= 1) m = fmaxf(m, __shfl_down_sync(0xffffffffu, m, o));
    if ((t & 31) == 0) red[t >> 5] = m;
    __syncthreads();
    if (t < 32) {
        float v = red[t];
#pragma unroll
        for (int o = 16; o > 0; o >>= 1) v = fmaxf(v, __shfl_down_sync(0xffffffffu, v, o));
        if (t == 0) g_maxadst[0] = v;
    }
}

// ===================================================================
// Kernel 4: fused masked softmax @ Xp, sigmoid epilogue.
// Block = 16 rows (i0..i0+15), 256 threads = 8 warps.
// Warp w owns j in [w*1024, (w+1)*1024). Per 32-j batch:
//   phase 1: per-lane j: mask, lrelu, threshold, exp -> p staged in smem
//   phase 2: ballot active j, broadcast p via smem, float4 FMA into regs
// Combine: smem 2-level tree + row sums, sigmoid, store.
// Dynamic smem layout (floats):
//   [0      , 8192 )  acc partials  4 x 16 x 128
//   [8192   , 12288)  p stage       8 x 16 x 32
//   [12288  , 12416)  l partials    8 x 16
//   [12416  , 12432)  asrc[16]
//   [12432  , 12448)  m[16]
//   [12448  , 12464)  Lrow[16]
// ===================================================================
#define SMEM_FLOATS 12464
#define SMEM_BYTES  (SMEM_FLOATS * 4)

__global__ void __launch_bounds__(256) attn_kernel(const int* __restrict__ adj,
                                                   float* __restrict__ out) {
    extern __shared__ float sm[];
    float* s_acc  = sm;
    float* s_p    = sm + 8192;
    float* s_l    = sm + 12288;
    float* s_asrc = sm + 12416;
    float* s_m    = sm + 12432;
    float* s_L    = sm + 12448;

    const int i0   = blockIdx.x * TI;
    const int tid  = threadIdx.x;
    const int w    = tid >> 5;
    const int lane = tid & 31;

    if (tid < TI) {
        float as = g_asrc[i0 + tid];
        s_asrc[tid] = as;
        float sx = as + g_maxadst[0];
        s_m[tid] = fmaxf(sx, SLOPE * sx);   // lrelu (slope<1)
    }
    __syncthreads();

    float4 acc[TI];
#pragma unroll
    for (int r = 0; r < TI; r++) acc[r] = make_float4(0.f, 0.f, 0.f, 0.f);
    float l[TI];
#pragma unroll
    for (int r = 0; r < TI; r++) l[r] = 0.f;

    float* myp = s_p + w * (TI * 32);
    const int jbeg = w * 1024;
    const int jend = jbeg + 1024;

    for (int jb = jbeg; jb < jend; jb += 32) {
        const int j = jb + lane;
        const float ad = __ldg(&g_adst[j]);
        unsigned act = 0;
#pragma unroll
        for (int r = 0; r < TI; r++) {
            const int i = i0 + r;
            const int a = __ldcs(&adj[i * NN + j]);   // streaming: don't pollute L2
            const float s = s_asrc[r] + ad;
            const float e = fmaxf(s, SLOPE * s);      // lrelu
            const float d = e - s_m[r];               // <= 0
            const bool diag = (j == i);
            const bool on = ((a != 0) | diag) && ((d > -THETA) | diag);
            float pr = 0.f;
            if (on) pr = __expf(d);
            myp[r * 32 + lane] = pr;
            l[r] += pr;
            act |= on ? (1u << r) : 0u;
        }
        __syncwarp();
        unsigned bal = __ballot_sync(0xffffffffu, act != 0u);
        while (bal) {
            const int jj = __ffs(bal) - 1;
            bal &= bal - 1;
            const float4 x = __ldg((const float4*)(g_Xp + (jb + jj) * FOUT) + lane);
#pragma unroll
            for (int r = 0; r < TI; r++) {
                const float pr = myp[r * 32 + jj];    // smem broadcast
                acc[r].x += pr * x.x;
                acc[r].y += pr * x.y;
                acc[r].z += pr * x.z;
                acc[r].w += pr * x.w;
            }
        }
        __syncwarp();
    }

    // per-warp l reduce -> s_l
#pragma unroll
    for (int r = 0; r < TI; r++) {
        float lr = l[r];
#pragma unroll
        for (int o = 16; o > 0; o >>= 1) lr += __shfl_down_sync(0xffffffffu, lr, o);
        if (lane == 0) s_l[w * TI + r] = lr;
    }

    // acc combine: warps 0-3 write, warps 4-7 add, then final 4-way sum
    if (w < 4) {
#pragma unroll
        for (int r = 0; r < TI; r++)
            *((float4*)(s_acc + (w * TI + r) * FOUT) + lane) = acc[r];
    }
    __syncthreads();
    if (w >= 4) {
#pragma unroll
        for (int r = 0; r < TI; r++) {
            float4* dst = (float4*)(s_acc + ((w - 4) * TI + r) * FOUT) + lane;
            float4 t = *dst;
            t.x += acc[r].x; t.y += acc[r].y; t.z += acc[r].z; t.w += acc[r].w;
            *dst = t;
        }
    }
    __syncthreads();
    if (tid < TI) {
        float L = 0.f;
#pragma unroll
        for (int ww = 0; ww < 8; ww++) L += s_l[ww * TI + tid];
        s_L[tid] = L;
    }
    __syncthreads();

    // 2048 outputs / 256 threads
#pragma unroll
    for (int o = tid; o < TI * FOUT; o += 256) {
        const int r = o >> 7;
        const int f = o & 127;
        float v = s_acc[(0 * TI + r) * FOUT + f]
                + s_acc[(1 * TI + r) * FOUT + f]
                + s_acc[(2 * TI + r) * FOUT + f]
                + s_acc[(3 * TI + r) * FOUT + f];
        v /= s_L[r];
        out[(i0 + r) * FOUT + f] = 1.f / (1.f + __expf(-v));
    }
}

// ===================================================================
extern "C" void kernel_launch(void* const* d_in, const int* in_sizes, int n_in,
                              void* d_out, int out_size) {
    const float* X   = (const float*)d_in[0];
    const int*   adj = (const int*)  d_in[1];
    const float* W   = (const float*)d_in[2];
    const float* b   = (const float*)d_in[3];
    const float* S   = (const float*)d_in[4];
    float* out = (float*)d_out;

    gemm_xp_kernel<<<dim3(FOUT / 64, NN / 64), dim3(16, 16)>>>(X, W, b);
    proj_kernel<<<(NN * 32) / 256, 256>>>(S);
    maxred_kernel<<<1, 1024>>>();

    cudaFuncSetAttribute(attn_kernel, cudaFuncAttributeMaxDynamicSharedMemorySize, SMEM_BYTES);
    attn_kernel<<<NN / TI, 256, SMEM_BYTES>>>(adj, out);
}

// round 3
// speedup vs baseline: 3.1558x; 3.1558x over previous
#include <cuda_runtime.h>
#include <cuda_fp16.h>
#include <math.h>
#include <stdint.h>

#define NN    8192
#define FIN   256
#define FOUT  128
#define JS    4                 // j-splits
#define JPB   (NN / JS)         // 2048 j per CTA
#define NT    (JPB / 128)       // 16 tiles per CTA

// ---------------- device scratch (no allocation allowed) ----------------
__device__ float    g_Xp[NN * FOUT];        // fp32 projected features
__device__ __half   g_XphT[(size_t)FOUT * NN];  // fp16 transposed [f][i]
__device__ float    g_asrc[NN], g_adst[NN];
__device__ float    g_F[NN], g_H[NN];       // per-j factors
__device__ float    g_T[NN], g_V[NN], g_R[NN]; // per-row factors
__device__ int      g_cand[64];
__device__ float    g_candval[64];
__device__ float    g_part[(size_t)JS * NN * FOUT];  // 16 MB partials
__device__ float    g_lpart[JS * NN];

// ---------------- helpers ----------------
__device__ __forceinline__ uint32_t smem_u32(const void* p) {
    uint32_t a;
    asm("{ .reg .u64 t; cvta.to.shared.u64 t, %1; cvt.u32.u64 %0, t; }" : "=r"(a) : "l"(p));
    return a;
}
#define LDSM4(r, addr)                                                          \
    asm volatile("ldmatrix.sync.aligned.m8n8.x4.shared.b16 {%0,%1,%2,%3}, [%4];" \
        : "=r"((r)[0]), "=r"((r)[1]), "=r"((r)[2]), "=r"((r)[3]) : "r"(addr))
#define MMA16816(d, a, b0, b1)                                                  \
    asm volatile("mma.sync.aligned.m16n8k16.row.col.f32.f16.f16.f32 "           \
        "{%0,%1,%2,%3},{%4,%5,%6,%7},{%8,%9},{%0,%1,%2,%3};"                    \
        : "+f"((d)[0]), "+f"((d)[1]), "+f"((d)[2]), "+f"((d)[3])                \
        : "r"((a)[0]), "r"((a)[1]), "r"((a)[2]), "r"((a)[3]), "r"(b0), "r"(b1))

// ===================================================================
// Kernel 1: Xp = X @ W^T + b ; also fp16 transpose g_XphT[f][i]
// ===================================================================
__global__ void gemm_xp_kernel(const float* __restrict__ X,
                               const float* __restrict__ W,
                               const float* __restrict__ b) {
    __shared__ float Xs[64][17];
    __shared__ float Ws[64][17];
    const int tx = threadIdx.x, ty = threadIdx.y;
    const int tid = ty * 16 + tx;
    const int row0 = blockIdx.y * 64;
    const int col0 = blockIdx.x * 64;
    const int lr = tid >> 2;
    const int lk = (tid & 3) * 4;

    float acc[4][4];
#pragma unroll
    for (int i = 0; i < 4; i++)
#pragma unroll
        for (int j = 0; j < 4; j++) acc[i][j] = 0.f;

    for (int kt = 0; kt < FIN; kt += 16) {
        float4 xv = *reinterpret_cast<const float4*>(&X[(row0 + lr) * FIN + kt + lk]);
        Xs[lr][lk + 0] = xv.x; Xs[lr][lk + 1] = xv.y;
        Xs[lr][lk + 2] = xv.z; Xs[lr][lk + 3] = xv.w;
        float4 wv = *reinterpret_cast<const float4*>(&W[(col0 + lr) * FIN + kt + lk]);
        Ws[lr][lk + 0] = wv.x; Ws[lr][lk + 1] = wv.y;
        Ws[lr][lk + 2] = wv.z; Ws[lr][lk + 3] = wv.w;
        __syncthreads();
#pragma unroll
        for (int k = 0; k < 16; ++k) {
            float a[4], w[4];
#pragma unroll
            for (int i = 0; i < 4; i++) a[i] = Xs[ty * 4 + i][k];
#pragma unroll
            for (int j = 0; j < 4; j++) w[j] = Ws[tx * 4 + j][k];
#pragma unroll
            for (int i = 0; i < 4; i++)
#pragma unroll
                for (int j = 0; j < 4; j++) acc[i][j] += a[i] * w[j];
        }
        __syncthreads();
    }
#pragma unroll
    for (int i = 0; i < 4; i++) {
        const int row = row0 + ty * 4 + i;
#pragma unroll
        for (int j = 0; j < 4; j++) {
            const int f = col0 + tx * 4 + j;
            const float v = acc[i][j] + b[f];
            g_Xp[row * FOUT + f] = v;
            g_XphT[(size_t)f * NN + row] = __float2half(v);
        }
    }
}

// ===================================================================
// Kernel 2: per-row projections a_src, a_dst
// ===================================================================
__global__ void proj_kernel(const float* __restrict__ S) {
    int gw   = (blockIdx.x * blockDim.x + threadIdx.x) >> 5;
    int lane = threadIdx.x & 31;
    if (gw >= NN) return;
    const float4 x  = *((const float4*)(g_Xp + gw * FOUT) + lane);
    const float4 s1 = *((const float4*)(S) + lane);
    const float4 s2 = *((const float4*)(S + FOUT) + lane);
    float ss = x.x * s1.x + x.y * s1.y + x.z * s1.z + x.w * s1.w;
    float sd = x.x * s2.x + x.y * s2.y + x.z * s2.z + x.w * s2.w;
#pragma unroll
    for (int o = 16; o > 0; o >>= 1) {
        ss += __shfl_down_sync(0xffffffffu, ss, o);
        sd += __shfl_down_sync(0xffffffffu, sd, o);
    }
    if (lane == 0) { g_asrc[gw] = ss; g_adst[gw] = sd; }
}

// ===================================================================
// Kernel 3: top-64 (value, index) of a_dst, descending. One block.
// ===================================================================
__global__ void top64_kernel() {
    __shared__ float sv[NN];
    __shared__ float rv[32];
    __shared__ int   ri[32];
    const int t = threadIdx.x;          // 1024
    const int w = t >> 5, lane = t & 31;
    for (int k = t; k < NN; k += 1024) sv[k] = g_adst[k];
    __syncthreads();
    for (int r = 0; r < 64; r++) {
        float bv = -3e38f; int bi = 0;
        for (int k = t; k < NN; k += 1024)
            if (sv[k] > bv) { bv = sv[k]; bi = k; }
#pragma unroll
        for (int o = 16; o > 0; o >>= 1) {
            float ov = __shfl_down_sync(0xffffffffu, bv, o);
            int   oi = __shfl_down_sync(0xffffffffu, bi, o);
            if (ov > bv) { bv = ov; bi = oi; }
        }
        if (lane == 0) { rv[w] = bv; ri[w] = bi; }
        __syncthreads();
        if (t < 32) {
            bv = rv[t]; bi = ri[t];
#pragma unroll
            for (int o = 16; o > 0; o >>= 1) {
                float ov = __shfl_down_sync(0xffffffffu, bv, o);
                int   oi = __shfl_down_sync(0xffffffffu, bi, o);
                if (ov > bv) { bv = ov; bi = oi; }
            }
            if (t == 0) {
                g_cand[r] = bi; g_candval[r] = bv;
                sv[bi] = -3e38f;
            }
        }
        __syncthreads();
    }
}

// ===================================================================
// Kernel 4: per-row factors from approximate masked row-max
// ===================================================================
__global__ void rowprep_kernel(const int* __restrict__ adj) {
    const int i = blockIdx.x * 256 + threadIdx.x;
    if (i >= NN) return;
    const float as = g_asrc[i];
    float rm = g_adst[i];                       // diag always accessible
    for (int c = 0; c < 64; c++) {
        const int j = g_cand[c];
        if (adj[(size_t)i * NN + j] != 0) { rm = fmaxf(rm, g_candval[c]); break; }
    }
    const float sm = as + rm;
    if (sm > 0.f) {
        g_T[i] = -as;
        g_V[i] = __expf(-0.99f * as - rm);
        g_R[i] = __expf(-rm);
    } else {
        g_T[i] = 3e38f;                          // always negative branch
        g_V[i] = __expf(-0.01f * rm);
        g_R[i] = 0.f;
    }
}

// ===================================================================
// Kernel 5: per-j factors  F = exp(ad), H = exp(0.01 ad)
// ===================================================================
__global__ void prepj_kernel() {
    const int j = blockIdx.x * 256 + threadIdx.x;
    if (j >= NN) return;
    const float ad = g_adst[j];
    g_F[j] = __expf(ad);
    g_H[j] = __expf(0.01f * ad);
}

// ===================================================================
// Kernel 6: fused P-construction + HMMA P@Xp
//   grid (64, JS); 256 threads / 8 warps; 128 i-rows x 2048 j per CTA.
//   dyn smem: Ps[128][136] fp16 | Bs[128][136] fp16 | s_l[128*16] | sT/sV/sR[128]
// ===================================================================
#define PS_OFF 0
#define BS_OFF 34816
#define SL_OFF 69632
#define ST_OFF 77824
#define SV_OFF 78336
#define SR_OFF 78848
#define SMEM_ATTN 79360
#define PSTR 136

__global__ void __launch_bounds__(256, 2)
attn_kernel(const int* __restrict__ adj) {
    extern __shared__ char smem[];
    __half* Ps  = (__half*)(smem + PS_OFF);
    __half* Bs  = (__half*)(smem + BS_OFF);
    float*  s_l = (float*)(smem + SL_OFF);
    float*  sT  = (float*)(smem + ST_OFF);
    float*  sV  = (float*)(smem + SV_OFF);
    float*  sR  = (float*)(smem + SR_OFF);
    const uint32_t ps_u = smem_u32(Ps);
    const uint32_t bs_u = smem_u32(Bs);

    const int tid  = threadIdx.x;
    const int w    = tid >> 5;
    const int lane = tid & 31;
    const int rq   = tid >> 4;        // 16 row-groups of 8
    const int jq   = tid & 15;        // 16 j-groups of 8
    const int wm   = w & 3;           // warp M slice (32 rows)
    const int wn   = w >> 2;          // warp N slice (64 cols)
    const int i0    = blockIdx.x * 128;
    const int js    = blockIdx.y;
    const int jbase = js * JPB;

    if (tid < 128) {
        sT[tid] = g_T[i0 + tid];
        sV[tid] = g_V[i0 + tid];
        sR[tid] = g_R[i0 + tid];
    }
    float acc[2][8][4];
#pragma unroll
    for (int mt = 0; mt < 2; mt++)
#pragma unroll
        for (int nf = 0; nf < 8; nf++)
#pragma unroll
            for (int q = 0; q < 4; q++) acc[mt][nf][q] = 0.f;
    float lacc[8];
#pragma unroll
    for (int rr = 0; rr < 8; rr++) lacc[rr] = 0.f;
    __syncthreads();

    for (int t = 0; t < NT; t++) {
        const int jt = jbase + t * 128;
        // ---- load B tile: Bs[f][k] row-major from g_XphT ----
        {
            const __half* src = g_XphT + (size_t)(tid >> 1) * NN + jt + (tid & 1) * 64;
            __half* dst = Bs + (tid >> 1) * PSTR + (tid & 1) * 64;
#pragma unroll
            for (int it = 0; it < 8; it++)
                *(uint4*)(dst + it * 8) = __ldg((const uint4*)(src + it * 8));
        }
        // ---- build P tile ----
        {
            const int jj0 = jt + jq * 8;
            float F[8], H[8], A[8];
            *(float4*)(F)     = __ldg((const float4*)(g_F + jj0));
            *(float4*)(F + 4) = __ldg((const float4*)(g_F + jj0 + 4));
            *(float4*)(H)     = __ldg((const float4*)(g_H + jj0));
            *(float4*)(H + 4) = __ldg((const float4*)(g_H + jj0 + 4));
            *(float4*)(A)     = __ldg((const float4*)(g_adst + jj0));
            *(float4*)(A + 4) = __ldg((const float4*)(g_adst + jj0 + 4));
            const int4* arow = (const int4*)(adj + (size_t)(i0 + rq * 8) * NN + jj0);
#pragma unroll
            for (int rr = 0; rr < 8; rr++) {
                const int i = i0 + rq * 8 + rr;
                const int4 m0 = __ldcs(arow + (size_t)rr * (NN / 4));
                const int4 m1 = __ldcs(arow + (size_t)rr * (NN / 4) + 1);
                const float T = sT[rq * 8 + rr];
                const float V = sV[rq * 8 + rr];
                const float R = sR[rq * 8 + rr];
                int mk[8] = { m0.x, m0.y, m0.z, m0.w, m1.x, m1.y, m1.z, m1.w };
                float p[8]; float ls = 0.f;
#pragma unroll
                for (int jj = 0; jj < 8; jj++) {
                    const float sel = (A[jj] > T) ? R * F[jj] : V * H[jj];
                    const bool on = (mk[jj] != 0) || (jj0 + jj == i);
                    p[jj] = on ? sel : 0.f;
                    ls += p[jj];
                }
                lacc[rr] += ls;
                uint4 st;
                __half2 h;
                h = __floats2half2_rn(p[0], p[1]); st.x = *(uint32_t*)&h;
                h = __floats2half2_rn(p[2], p[3]); st.y = *(uint32_t*)&h;
                h = __floats2half2_rn(p[4], p[5]); st.z = *(uint32_t*)&h;
                h = __floats2half2_rn(p[6], p[7]); st.w = *(uint32_t*)&h;
                *(uint4*)(Ps + (rq * 8 + rr) * PSTR + jq * 8) = st;
            }
        }
        __syncthreads();
        // ---- MMA phase ----
        {
            const int m0r = wm * 32;
            const int n0  = wn * 64;
#pragma unroll
            for (int ks = 0; ks < 8; ks++) {
                uint32_t a[2][4];
#pragma unroll
                for (int mt = 0; mt < 2; mt++) {
                    const uint32_t addr = ps_u + 2 * ((m0r + mt * 16 + (lane & 15)) * PSTR
                                                      + ks * 16 + (lane >> 4) * 8);
                    LDSM4(a[mt], addr);
                }
#pragma unroll
                for (int nt = 0; nt < 4; nt++) {
                    uint32_t b[4];
                    const uint32_t addr = bs_u + 2 * ((n0 + nt * 16 + (lane & 7) + ((lane >> 4) << 3)) * PSTR
                                                      + ks * 16 + ((lane >> 3) & 1) * 8);
                    LDSM4(b, addr);
#pragma unroll
                    for (int mt = 0; mt < 2; mt++) {
                        MMA16816(acc[mt][nt * 2 + 0], a[mt], b[0], b[1]);
                        MMA16816(acc[mt][nt * 2 + 1], a[mt], b[2], b[3]);
                    }
                }
            }
        }
        __syncthreads();
    }

    // ---- epilogue: write accumulators + row sums ----
    {
        float* dst = g_part + ((size_t)js * NN + i0) * FOUT;
        const int rbase = wm * 32 + (lane >> 2);
        const int cbase = wn * 64 + (lane & 3) * 2;
#pragma unroll
        for (int mt = 0; mt < 2; mt++) {
#pragma unroll
            for (int nf = 0; nf < 8; nf++) {
                const int r = rbase + mt * 16;
                const int c = cbase + nf * 8;
                *(float2*)(dst + (size_t)r * FOUT + c) =
                    make_float2(acc[mt][nf][0], acc[mt][nf][1]);
                *(float2*)(dst + (size_t)(r + 8) * FOUT + c) =
                    make_float2(acc[mt][nf][2], acc[mt][nf][3]);
            }
        }
    }
#pragma unroll
    for (int rr = 0; rr < 8; rr++) s_l[(rq * 8 + rr) * 16 + jq] = lacc[rr];
    __syncthreads();
    if (tid < 128) {
        float L = 0.f;
#pragma unroll
        for (int q = 0; q < 16; q++) L += s_l[tid * 16 + q];
        g_lpart[js * NN + i0 + tid] = L;
    }
}

// ===================================================================
// Kernel 7: combine partials, divide, sigmoid
// ===================================================================
__global__ void combine_kernel(float* __restrict__ out) {
    const int gid = blockIdx.x * 256 + threadIdx.x;   // float4 units
    const int i = gid >> 5;
    const int c = gid & 31;
    float4 s = make_float4(0.f, 0.f, 0.f, 0.f);
    float L = 0.f;
#pragma unroll
    for (int js = 0; js < JS; js++) {
        const float4 a = *(const float4*)(g_part + ((size_t)js * NN + i) * FOUT + c * 4);
        s.x += a.x; s.y += a.y; s.z += a.z; s.w += a.w;
        L += g_lpart[js * NN + i];
    }
    const float inv = 1.f / L;
    float4 o;
    o.x = 1.f / (1.f + __expf(-s.x * inv));
    o.y = 1.f / (1.f + __expf(-s.y * inv));
    o.z = 1.f / (1.f + __expf(-s.z * inv));
    o.w = 1.f / (1.f + __expf(-s.w * inv));
    *(float4*)(out + (size_t)i * FOUT + c * 4) = o;
}

// ===================================================================
extern "C" void kernel_launch(void* const* d_in, const int* in_sizes, int n_in,
                              void* d_out, int out_size) {
    const float* X   = (const float*)d_in[0];
    const int*   adj = (const int*)  d_in[1];
    const float* W   = (const float*)d_in[2];
    const float* b   = (const float*)d_in[3];
    const float* S   = (const float*)d_in[4];
    float* out = (float*)d_out;

    gemm_xp_kernel<<<dim3(FOUT / 64, NN / 64), dim3(16, 16)>>>(X, W, b);
    proj_kernel<<<(NN * 32) / 256, 256>>>(S);
    top64_kernel<<<1, 1024>>>();
    rowprep_kernel<<<NN / 256, 256>>>(adj);
    prepj_kernel<<<NN / 256, 256>>>();

    cudaFuncSetAttribute(attn_kernel, cudaFuncAttributeMaxDynamicSharedMemorySize, SMEM_ATTN);
    attn_kernel<<<dim3(NN / 128, JS), 256, SMEM_ATTN>>>(adj);
    combine_kernel<<<(NN * 32) / 256, 256>>>(out);
}

// round 4
// speedup vs baseline: 3.4448x; 1.0916x over previous
#include <cuda_runtime.h>
#include <cuda_fp16.h>
#include <math.h>
#include <stdint.h>

#define NN    8192
#define FIN   256
#define FOUT  128
#define JS    4                 // j-splits
#define JPB   (NN / JS)         // 2048 j per CTA
#define NT    (JPB / 128)       // 16 tiles per CTA
#define PSTR  136
#define PS_BYTES (128 * PSTR * 2)   // 34816

// ---------------- device scratch (no allocation allowed) ----------------
__device__ float    g_Xp[NN * FOUT];
__device__ __half   g_XphT[(size_t)FOUT * NN];  // fp16 transposed [f][i]
__device__ float    g_asrc[NN], g_adst[NN];
__device__ float    g_F[NN], g_H[NN];
__device__ float    g_T[NN], g_V[NN], g_R[NN];
__device__ int      g_cand[256];
__device__ float    g_candval[256];
__device__ int      g_ccount;
__device__ float    g_tau;
__device__ float    g_part[(size_t)JS * NN * FOUT];
__device__ float    g_lpart[JS * NN];

// ---------------- helpers ----------------
__device__ __forceinline__ uint32_t smem_u32(const void* p) {
    uint32_t a;
    asm("{ .reg .u64 t; cvta.to.shared.u64 t, %1; cvt.u32.u64 %0, t; }" : "=r"(a) : "l"(p));
    return a;
}
#define LDSM4(r, addr)                                                          \
    asm volatile("ldmatrix.sync.aligned.m8n8.x4.shared.b16 {%0,%1,%2,%3}, [%4];" \
        : "=r"((r)[0]), "=r"((r)[1]), "=r"((r)[2]), "=r"((r)[3]) : "r"(addr))
#define MMA16816(d, a, b0, b1)                                                  \
    asm volatile("mma.sync.aligned.m16n8k16.row.col.f32.f16.f16.f32 "           \
        "{%0,%1,%2,%3},{%4,%5,%6,%7},{%8,%9},{%0,%1,%2,%3};"                    \
        : "+f"((d)[0]), "+f"((d)[1]), "+f"((d)[2]), "+f"((d)[3])                \
        : "r"((a)[0]), "r"((a)[1]), "r"((a)[2]), "r"((a)[3]), "r"(b0), "r"(b1))
#define CP_ASYNC16(dst, src) \
    asm volatile("cp.async.cg.shared.global [%0], [%1], 16;" :: "r"(dst), "l"(src))
#define CP_COMMIT() asm volatile("cp.async.commit_group;" ::: "memory")
#define CP_WAIT0()  asm volatile("cp.async.wait_group 0;" ::: "memory")

// ===================================================================
// Kernel 1: Xp = X @ W^T + b ; fp16 transpose g_XphT[f][i]
// ===================================================================
__global__ void gemm_xp_kernel(const float* __restrict__ X,
                               const float* __restrict__ W,
                               const float* __restrict__ b) {
    __shared__ float Xs[64][17];
    __shared__ float Ws[64][17];
    const int tx = threadIdx.x, ty = threadIdx.y;
    const int tid = ty * 16 + tx;
    const int row0 = blockIdx.y * 64;
    const int col0 = blockIdx.x * 64;
    const int lr = tid >> 2;
    const int lk = (tid & 3) * 4;

    float acc[4][4];
#pragma unroll
    for (int i = 0; i < 4; i++)
#pragma unroll
        for (int j = 0; j < 4; j++) acc[i][j] = 0.f;

    for (int kt = 0; kt < FIN; kt += 16) {
        float4 xv = *reinterpret_cast<const float4*>(&X[(row0 + lr) * FIN + kt + lk]);
        Xs[lr][lk + 0] = xv.x; Xs[lr][lk + 1] = xv.y;
        Xs[lr][lk + 2] = xv.z; Xs[lr][lk + 3] = xv.w;
        float4 wv = *reinterpret_cast<const float4*>(&W[(col0 + lr) * FIN + kt + lk]);
        Ws[lr][lk + 0] = wv.x; Ws[lr][lk + 1] = wv.y;
        Ws[lr][lk + 2] = wv.z; Ws[lr][lk + 3] = wv.w;
        __syncthreads();
#pragma unroll
        for (int k = 0; k < 16; ++k) {
            float a[4], w[4];
#pragma unroll
            for (int i = 0; i < 4; i++) a[i] = Xs[ty * 4 + i][k];
#pragma unroll
            for (int j = 0; j < 4; j++) w[j] = Ws[tx * 4 + j][k];
#pragma unroll
            for (int i = 0; i < 4; i++)
#pragma unroll
                for (int j = 0; j < 4; j++) acc[i][j] += a[i] * w[j];
        }
        __syncthreads();
    }
#pragma unroll
    for (int i = 0; i < 4; i++) {
        const int row = row0 + ty * 4 + i;
#pragma unroll
        for (int j = 0; j < 4; j++) {
            const int f = col0 + tx * 4 + j;
            const float v = acc[i][j] + b[f];
            g_Xp[row * FOUT + f] = v;
            g_XphT[(size_t)f * NN + row] = __float2half(v);
        }
    }
}

// ===================================================================
// Kernel 2: per-row projections a_src, a_dst
// ===================================================================
__global__ void proj_kernel(const float* __restrict__ S) {
    int gw   = (blockIdx.x * blockDim.x + threadIdx.x) >> 5;
    int lane = threadIdx.x & 31;
    if (gw >= NN) return;
    const float4 x  = *((const float4*)(g_Xp + gw * FOUT) + lane);
    const float4 s1 = *((const float4*)(S) + lane);
    const float4 s2 = *((const float4*)(S + FOUT) + lane);
    float ss = x.x * s1.x + x.y * s1.y + x.z * s1.z + x.w * s1.w;
    float sd = x.x * s2.x + x.y * s2.y + x.z * s2.z + x.w * s2.w;
#pragma unroll
    for (int o = 16; o > 0; o >>= 1) {
        ss += __shfl_down_sync(0xffffffffu, ss, o);
        sd += __shfl_down_sync(0xffffffffu, sd, o);
    }
    if (lane == 0) { g_asrc[gw] = ss; g_adst[gw] = sd; }
}

// ===================================================================
// Kernel 3: global max + histogram -> threshold tau covering >=96 top values
// ===================================================================
__global__ void hist_kernel() {
    __shared__ float red[32];
    __shared__ int   hist[128];
    __shared__ float smx;
    const int t = threadIdx.x;  // 1024
    float m = -3e38f;
    for (int i = t; i < NN; i += 1024) m = fmaxf(m, g_adst[i]);
#pragma unroll
    for (int o = 16; o > 0; o >>= 1) m = fmaxf(m, __shfl_down_sync(0xffffffffu, m, o));
    if ((t & 31) == 0) red[t >> 5] = m;
    if (t < 128) hist[t] = 0;
    __syncthreads();
    if (t < 32) {
        float v = red[t];
#pragma unroll
        for (int o = 16; o > 0; o >>= 1) v = fmaxf(v, __shfl_down_sync(0xffffffffu, v, o));
        if (t == 0) smx = v;
    }
    __syncthreads();
    const float mx = smx;
    for (int i = t; i < NN; i += 1024) {
        const float v = g_adst[i];
        if (v >= mx - 20.f) {
            int bin = (int)((mx - v) * (128.f / 20.f));
            bin = bin < 127 ? bin : 127;
            atomicAdd(&hist[bin], 1);
        }
    }
    __syncthreads();
    if (t == 0) {
        int cum = 0;
        float tau = mx - 20.f;
        for (int b2 = 0; b2 < 128; b2++) {
            cum += hist[b2];
            if (cum >= 96) { tau = mx - (float)(b2 + 1) * (20.f / 128.f); break; }
        }
        g_tau = tau;
        g_ccount = 0;
    }
}

// ===================================================================
// Kernel 4: collect candidates >= tau (unordered); also F/H factors
// ===================================================================
__global__ void collect_kernel() {
    const int j = blockIdx.x * 256 + threadIdx.x;
    const float v = g_adst[j];
    g_F[j] = __expf(v);
    g_H[j] = __expf(0.01f * v);
    if (v >= g_tau) {
        const int p = atomicAdd(&g_ccount, 1);
        if (p < 256) { g_cand[p] = j; g_candval[p] = v; }
    }
}

// ===================================================================
// Kernel 5: per-row factors from exact masked row-max over candidates
// ===================================================================
__global__ void rowprep_kernel(const int* __restrict__ adj) {
    __shared__ int   scand[256];
    __shared__ float scval[256];
    __shared__ int   scount;
    const int t = threadIdx.x;
    if (t == 0) { int c = g_ccount; scount = c < 256 ? c : 256; }
    scand[t] = g_cand[t];
    scval[t] = g_candval[t];
    __syncthreads();
    const int i = blockIdx.x * 256 + t;
    const float as = g_asrc[i];
    float rm = g_adst[i];                     // diag always accessible
    const int n = scount;
    const int* arow = adj + (size_t)i * NN;
#pragma unroll 8
    for (int c = 0; c < n; c++) {
        if (__ldg(&arow[scand[c]]) != 0) rm = fmaxf(rm, scval[c]);
    }
    const float sm = as + rm;
    if (sm > 0.f) {
        g_T[i] = -as;
        g_V[i] = __expf(-0.99f * as - rm);
        g_R[i] = __expf(-rm);
    } else {
        g_T[i] = 3e38f;
        g_V[i] = __expf(-0.01f * rm);
        g_R[i] = 0.f;
    }
}

// ===================================================================
// Kernel 6: fused pipelined P-construction + HMMA P@Xp
//   grid (64, JS); 256 threads / 8 warps; occ 1 (register-rich)
//   smem: Ps @0 (34816) | Bs[2] @34816 (2x34816) | sT/sV/sR @104448
// ===================================================================
#define BS_OFF   34816
#define ST_OFF   104448
#define SV_OFF   104960
#define SR_OFF   105472
#define SMEM_ATTN 105984

struct AdjRegs { int4 v[8]; };  // 4 rows x 2 int4 (32 j)

__device__ __forceinline__ void load_adj4(AdjRegs& r, const int4* __restrict__ adj4,
                                          size_t base4, int row0) {
#pragma unroll
    for (int rr = 0; rr < 4; rr++) {
        r.v[2 * rr]     = __ldcs(adj4 + base4 + (size_t)(row0 + rr) * (NN / 4));
        r.v[2 * rr + 1] = __ldcs(adj4 + base4 + (size_t)(row0 + rr) * (NN / 4) + 1);
    }
}

__device__ __forceinline__ void build4(const AdjRegs& r, int row0,
                                       const float* F, const float* H, const float* A,
                                       const float* sT, const float* sV, const float* sR,
                                       __half* Ps, float* lacc,
                                       int rqbase, int jq, int jj0, int i0) {
#pragma unroll
    for (int rr = 0; rr < 4; rr++) {
        const int row = rqbase + row0 + rr;
        const int i = i0 + row;
        const int* mk = (const int*)&r.v[2 * rr];
        const float T = sT[row], V = sV[row], R = sR[row];
        float p[8]; float ls = 0.f;
#pragma unroll
        for (int jj = 0; jj < 8; jj++) {
            float sel = (A[jj] > T) ? R * F[jj] : V * H[jj];
            sel = fminf(sel, 60000.f);
            const bool on = (mk[jj] != 0) || (jj0 + jj == i);
            p[jj] = on ? sel : 0.f;
            ls += p[jj];
        }
        lacc[row0 + rr] += ls;
        uint4 st;
        __half2 h;
        h = __floats2half2_rn(p[0], p[1]); st.x = *(uint32_t*)&h;
        h = __floats2half2_rn(p[2], p[3]); st.y = *(uint32_t*)&h;
        h = __floats2half2_rn(p[4], p[5]); st.z = *(uint32_t*)&h;
        h = __floats2half2_rn(p[6], p[7]); st.w = *(uint32_t*)&h;
        *(uint4*)(Ps + row * PSTR + jq * 8) = st;
    }
}

__device__ __forceinline__ void mma_tile(uint32_t ps_u, uint32_t bs_u,
                                         int wm, int wn, int lane,
                                         float acc[2][8][4]) {
    const int m0r = wm * 32;
    const int n0  = wn * 64;
#pragma unroll
    for (int ks = 0; ks < 8; ks++) {
        uint32_t a[2][4];
#pragma unroll
        for (int mt = 0; mt < 2; mt++) {
            const uint32_t addr = ps_u + 2 * ((m0r + mt * 16 + (lane & 15)) * PSTR
                                              + ks * 16 + (lane >> 4) * 8);
            LDSM4(a[mt], addr);
        }
#pragma unroll
        for (int nt = 0; nt < 4; nt++) {
            uint32_t b[4];
            const uint32_t addr = bs_u + 2 * ((n0 + nt * 16 + (lane & 7) + ((lane >> 4) << 3)) * PSTR
                                              + ks * 16 + ((lane >> 3) & 1) * 8);
            LDSM4(b, addr);
#pragma unroll
            for (int mt = 0; mt < 2; mt++) {
                MMA16816(acc[mt][nt * 2 + 0], a[mt], b[0], b[1]);
                MMA16816(acc[mt][nt * 2 + 1], a[mt], b[2], b[3]);
            }
        }
    }
}

__global__ void __launch_bounds__(256, 1)
attn_kernel(const int* __restrict__ adj) {
    extern __shared__ char smem[];
    __half* Ps  = (__half*)(smem);
    float*  sT  = (float*)(smem + ST_OFF);
    float*  sV  = (float*)(smem + SV_OFF);
    float*  sR  = (float*)(smem + SR_OFF);
    const uint32_t ps_u  = smem_u32(smem);
    const uint32_t bs_u0 = ps_u + BS_OFF;

    const int tid  = threadIdx.x;
    const int w    = tid >> 5;
    const int lane = tid & 31;
    const int rq   = tid >> 4;        // 16 row-groups of 8
    const int jq   = tid & 15;        // 16 j-groups of 8
    const int wm   = w & 3;
    const int wn   = w >> 2;
    const int i0    = blockIdx.x * 128;
    const int js    = blockIdx.y;
    const int jbase = js * JPB;

    if (tid < 128) {
        sT[tid] = g_T[i0 + tid];
        sV[tid] = g_V[i0 + tid];
        sR[tid] = g_R[i0 + tid];
    }
    float acc[2][8][4];
#pragma unroll
    for (int mt = 0; mt < 2; mt++)
#pragma unroll
        for (int nf = 0; nf < 8; nf++)
#pragma unroll
            for (int q = 0; q < 4; q++) acc[mt][nf][q] = 0.f;
    float lacc[8];
#pragma unroll
    for (int rr = 0; rr < 8; rr++) lacc[rr] = 0.f;

    const int4* adj4 = (const int4*)adj;
    const size_t brow = (size_t)(i0 + rq * 8) * (NN / 4) + (size_t)((jbase + jq * 8) >> 2);

    // issue B(t) into buffer t&1
    const __half* bsrc0 = g_XphT + (size_t)(tid >> 1) * NN + jbase + (tid & 1) * 64;
    const uint32_t bdst0 = bs_u0 + (uint32_t)(tid >> 1) * (PSTR * 2) + (uint32_t)(tid & 1) * 128;
#define ISSUE_B(t)                                                              \
    do {                                                                        \
        const char* _s = (const char*)(bsrc0 + (t) * 128);                      \
        const uint32_t _d = bdst0 + ((t) & 1) * PS_BYTES;                       \
        _Pragma("unroll")                                                       \
        for (int _it = 0; _it < 8; _it++) CP_ASYNC16(_d + _it * 16, _s + _it * 16); \
        CP_COMMIT();                                                            \
    } while (0)

    AdjRegs pfA, pfB, tmp;
    ISSUE_B(0);
    load_adj4(pfA, adj4, brow, 0);    // tile 0, rows 0-3

    float Fv[8], Hv[8], Av[8];
#define LOAD_FHA(t)                                                             \
    do {                                                                        \
        const int _j = jbase + (t) * 128 + jq * 8;                              \
        *(float4*)(Fv)     = __ldg((const float4*)(g_F + _j));                  \
        *(float4*)(Fv + 4) = __ldg((const float4*)(g_F + _j + 4));              \
        *(float4*)(Hv)     = __ldg((const float4*)(g_H + _j));                  \
        *(float4*)(Hv + 4) = __ldg((const float4*)(g_H + _j + 4));              \
        *(float4*)(Av)     = __ldg((const float4*)(g_adst + _j));               \
        *(float4*)(Av + 4) = __ldg((const float4*)(g_adst + _j + 4));           \
    } while (0)

#pragma unroll 1
    for (int tt = 0; tt < NT / 2; tt++) {
        const int t0 = 2 * tt, t1 = 2 * tt + 1;
        // ---------- tile t0 (even: P from pfA, prefetch into pfB) ----------
        CP_WAIT0();
        __syncthreads();                              // B(t0) visible; MMA(t0-1) done
        ISSUE_B(t1);
        load_adj4(tmp, adj4, brow + (size_t)(t0 * 32), 4);   // t0 rows 4-7
        load_adj4(pfB, adj4, brow + (size_t)(t1 * 32), 0);   // t1 rows 0-3
        LOAD_FHA(t0);
        {
            const int jj0 = jbase + t0 * 128 + jq * 8;
            build4(pfA, 0, Fv, Hv, Av, sT, sV, sR, Ps, lacc, rq * 8, jq, jj0, i0);
            build4(tmp, 4, Fv, Hv, Av, sT, sV, sR, Ps, lacc, rq * 8, jq, jj0, i0);
        }
        __syncthreads();                              // Ps ready
        mma_tile(ps_u, bs_u0 + (t0 & 1) * PS_BYTES, wm, wn, lane, acc);

        // ---------- tile t1 (odd: P from pfB, prefetch into pfA) ----------
        CP_WAIT0();
        __syncthreads();
        if (t1 + 1 < NT) ISSUE_B(t1 + 1);
        load_adj4(tmp, adj4, brow + (size_t)(t1 * 32), 4);   // t1 rows 4-7
        if (t1 + 1 < NT)
            load_adj4(pfA, adj4, brow + (size_t)((t1 + 1) * 32), 0);
        LOAD_FHA(t1);
        {
            const int jj0 = jbase + t1 * 128 + jq * 8;
            build4(pfB, 0, Fv, Hv, Av, sT, sV, sR, Ps, lacc, rq * 8, jq, jj0, i0);
            build4(tmp, 4, Fv, Hv, Av, sT, sV, sR, Ps, lacc, rq * 8, jq, jj0, i0);
        }
        __syncthreads();
        mma_tile(ps_u, bs_u0 + (t1 & 1) * PS_BYTES, wm, wn, lane, acc);
    }

    // ---- epilogue ----
    {
        float* dst = g_part + ((size_t)js * NN + i0) * FOUT;
        const int rbase = wm * 32 + (lane >> 2);
        const int cbase = wn * 64 + (lane & 3) * 2;
#pragma unroll
        for (int mt = 0; mt < 2; mt++) {
#pragma unroll
            for (int nf = 0; nf < 8; nf++) {
                const int r = rbase + mt * 16;
                const int c = cbase + nf * 8;
                *(float2*)(dst + (size_t)r * FOUT + c) =
                    make_float2(acc[mt][nf][0], acc[mt][nf][1]);
                *(float2*)(dst + (size_t)(r + 8) * FOUT + c) =
                    make_float2(acc[mt][nf][2], acc[mt][nf][3]);
            }
        }
    }
    // row sums: alias scratch into Bs buffer 0 (free: last MMA read buffer 1 & Ps)
    float* s_l = (float*)(smem + BS_OFF);
#pragma unroll
    for (int rr = 0; rr < 8; rr++) s_l[(rq * 8 + rr) * 16 + jq] = lacc[rr];
    __syncthreads();
    if (tid < 128) {
        float L = 0.f;
#pragma unroll
        for (int q = 0; q < 16; q++) L += s_l[tid * 16 + q];
        g_lpart[js * NN + i0 + tid] = L;
    }
}

// ===================================================================
// Kernel 7: combine partials, divide, sigmoid
// ===================================================================
__global__ void combine_kernel(float* __restrict__ out) {
    const int gid = blockIdx.x * 256 + threadIdx.x;
    const int i = gid >> 5;
    const int c = gid & 31;
    float4 s = make_float4(0.f, 0.f, 0.f, 0.f);
    float L = 0.f;
#pragma unroll
    for (int js = 0; js < JS; js++) {
        const float4 a = *(const float4*)(g_part + ((size_t)js * NN + i) * FOUT + c * 4);
        s.x += a.x; s.y += a.y; s.z += a.z; s.w += a.w;
        L += g_lpart[js * NN + i];
    }
    const float inv = 1.f / L;
    float4 o;
    o.x = 1.f / (1.f + __expf(-s.x * inv));
    o.y = 1.f / (1.f + __expf(-s.y * inv));
    o.z = 1.f / (1.f + __expf(-s.z * inv));
    o.w = 1.f / (1.f + __expf(-s.w * inv));
    *(float4*)(out + (size_t)i * FOUT + c * 4) = o;
}

// ===================================================================
extern "C" void kernel_launch(void* const* d_in, const int* in_sizes, int n_in,
                              void* d_out, int out_size) {
    const float* X   = (const float*)d_in[0];
    const int*   adj = (const int*)  d_in[1];
    const float* W   = (const float*)d_in[2];
    const float* b   = (const float*)d_in[3];
    const float* S   = (const float*)d_in[4];
    float* out = (float*)d_out;

    gemm_xp_kernel<<<dim3(FOUT / 64, NN / 64), dim3(16, 16)>>>(X, W, b);
    proj_kernel<<<(NN * 32) / 256, 256>>>(S);
    hist_kernel<<<1, 1024>>>();
    collect_kernel<<<NN / 256, 256>>>();
    rowprep_kernel<<<NN / 256, 256>>>(adj);

    cudaFuncSetAttribute(attn_kernel, cudaFuncAttributeMaxDynamicSharedMemorySize, SMEM_ATTN);
    attn_kernel<<<dim3(NN / 128, JS), 256, SMEM_ATTN>>>(adj);
    combine_kernel<<<(NN * 32) / 256, 256>>>(out);
}

// round 5
// speedup vs baseline: 3.4705x; 1.0075x over previous
#include <cuda_runtime.h>
#include <cuda_fp16.h>
#include <math.h>
#include <stdint.h>

#define NN    8192
#define FIN   256
#define FOUT  128
#define JS    4                 // j-splits
#define JPB   (NN / JS)         // 2048 j per CTA
#define NT    (JPB / 128)       // 16 tiles per CTA
#define PSTR  136
#define PS_BYTES (128 * PSTR * 2)   // 34816

// ---------------- device scratch (no allocation allowed) ----------------
__device__ float    g_Xp[NN * FOUT];
__device__ __half   g_XphT[(size_t)FOUT * NN];  // fp16 transposed [f][i]
__device__ float    g_asrc[NN], g_adst[NN];
__device__ float    g_F[NN], g_H[NN];
__device__ float    g_T[NN], g_V[NN], g_R[NN];
__device__ int      g_cand[256];
__device__ float    g_candval[256];
__device__ int      g_ccount;
__device__ float    g_tau;
__device__ float    g_part[(size_t)JS * NN * FOUT];
__device__ float    g_lpart[JS * NN];

// ---------------- helpers ----------------
__device__ __forceinline__ uint32_t smem_u32(const void* p) {
    uint32_t a;
    asm("{ .reg .u64 t; cvta.to.shared.u64 t, %1; cvt.u32.u64 %0, t; }" : "=r"(a) : "l"(p));
    return a;
}
#define LDSM4(r, addr)                                                          \
    asm volatile("ldmatrix.sync.aligned.m8n8.x4.shared.b16 {%0,%1,%2,%3}, [%4];" \
        : "=r"((r)[0]), "=r"((r)[1]), "=r"((r)[2]), "=r"((r)[3]) : "r"(addr))
#define MMA16816(d, a, b0, b1)                                                  \
    asm volatile("mma.sync.aligned.m16n8k16.row.col.f32.f16.f16.f32 "           \
        "{%0,%1,%2,%3},{%4,%5,%6,%7},{%8,%9},{%0,%1,%2,%3};"                    \
        : "+f"((d)[0]), "+f"((d)[1]), "+f"((d)[2]), "+f"((d)[3])                \
        : "r"((a)[0]), "r"((a)[1]), "r"((a)[2]), "r"((a)[3]), "r"(b0), "r"(b1))
#define CP_ASYNC16(dst, src) \
    asm volatile("cp.async.cg.shared.global [%0], [%1], 16;" :: "r"(dst), "l"(src))
#define CP_COMMIT() asm volatile("cp.async.commit_group;" ::: "memory")
#define CP_WAIT0()  asm volatile("cp.async.wait_group 0;" ::: "memory")

// ===================================================================
// Kernel 1: Xp = X @ W^T + b ; fp16 transpose g_XphT[f][i]
// ===================================================================
__global__ void gemm_xp_kernel(const float* __restrict__ X,
                               const float* __restrict__ W,
                               const float* __restrict__ b) {
    __shared__ float Xs[64][17];
    __shared__ float Ws[64][17];
    const int tx = threadIdx.x, ty = threadIdx.y;
    const int tid = ty * 16 + tx;
    const int row0 = blockIdx.y * 64;
    const int col0 = blockIdx.x * 64;
    const int lr = tid >> 2;
    const int lk = (tid & 3) * 4;

    float acc[4][4];
#pragma unroll
    for (int i = 0; i < 4; i++)
#pragma unroll
        for (int j = 0; j < 4; j++) acc[i][j] = 0.f;

    for (int kt = 0; kt < FIN; kt += 16) {
        float4 xv = *reinterpret_cast<const float4*>(&X[(row0 + lr) * FIN + kt + lk]);
        Xs[lr][lk + 0] = xv.x; Xs[lr][lk + 1] = xv.y;
        Xs[lr][lk + 2] = xv.z; Xs[lr][lk + 3] = xv.w;
        float4 wv = *reinterpret_cast<const float4*>(&W[(col0 + lr) * FIN + kt + lk]);
        Ws[lr][lk + 0] = wv.x; Ws[lr][lk + 1] = wv.y;
        Ws[lr][lk + 2] = wv.z; Ws[lr][lk + 3] = wv.w;
        __syncthreads();
#pragma unroll
        for (int k = 0; k < 16; ++k) {
            float a[4], w[4];
#pragma unroll
            for (int i = 0; i < 4; i++) a[i] = Xs[ty * 4 + i][k];
#pragma unroll
            for (int j = 0; j < 4; j++) w[j] = Ws[tx * 4 + j][k];
#pragma unroll
            for (int i = 0; i < 4; i++)
#pragma unroll
                for (int j = 0; j < 4; j++) acc[i][j] += a[i] * w[j];
        }
        __syncthreads();
    }
#pragma unroll
    for (int i = 0; i < 4; i++) {
        const int row = row0 + ty * 4 + i;
#pragma unroll
        for (int j = 0; j < 4; j++) {
            const int f = col0 + tx * 4 + j;
            const float v = acc[i][j] + b[f];
            g_Xp[row * FOUT + f] = v;
            g_XphT[(size_t)f * NN + row] = __float2half(v);
        }
    }
}

// ===================================================================
// Kernel 2: per-row projections a_src, a_dst
// ===================================================================
__global__ void proj_kernel(const float* __restrict__ S) {
    int gw   = (blockIdx.x * blockDim.x + threadIdx.x) >> 5;
    int lane = threadIdx.x & 31;
    if (gw >= NN) return;
    const float4 x  = *((const float4*)(g_Xp + gw * FOUT) + lane);
    const float4 s1 = *((const float4*)(S) + lane);
    const float4 s2 = *((const float4*)(S + FOUT) + lane);
    float ss = x.x * s1.x + x.y * s1.y + x.z * s1.z + x.w * s1.w;
    float sd = x.x * s2.x + x.y * s2.y + x.z * s2.z + x.w * s2.w;
#pragma unroll
    for (int o = 16; o > 0; o >>= 1) {
        ss += __shfl_down_sync(0xffffffffu, ss, o);
        sd += __shfl_down_sync(0xffffffffu, sd, o);
    }
    if (lane == 0) { g_asrc[gw] = ss; g_adst[gw] = sd; }
}

// ===================================================================
// Kernel 3: global max + histogram -> threshold tau covering >=96 top values
// ===================================================================
__global__ void hist_kernel() {
    __shared__ float red[32];
    __shared__ int   hist[128];
    __shared__ float smx;
    const int t = threadIdx.x;  // 1024
    float m = -3e38f;
    for (int i = t; i < NN; i += 1024) m = fmaxf(m, g_adst[i]);
#pragma unroll
    for (int o = 16; o > 0; o >>= 1) m = fmaxf(m, __shfl_down_sync(0xffffffffu, m, o));
    if ((t & 31) == 0) red[t >> 5] = m;
    if (t < 128) hist[t] = 0;
    __syncthreads();
    if (t < 32) {
        float v = red[t];
#pragma unroll
        for (int o = 16; o > 0; o >>= 1) v = fmaxf(v, __shfl_down_sync(0xffffffffu, v, o));
        if (t == 0) smx = v;
    }
    __syncthreads();
    const float mx = smx;
    for (int i = t; i < NN; i += 1024) {
        const float v = g_adst[i];
        if (v >= mx - 20.f) {
            int bin = (int)((mx - v) * (128.f / 20.f));
            bin = bin < 127 ? bin : 127;
            atomicAdd(&hist[bin], 1);
        }
    }
    __syncthreads();
    if (t == 0) {
        int cum = 0;
        float tau = mx - 20.f;
        for (int b2 = 0; b2 < 128; b2++) {
            cum += hist[b2];
            if (cum >= 96) { tau = mx - (float)(b2 + 1) * (20.f / 128.f); break; }
        }
        g_tau = tau;
        g_ccount = 0;
    }
}

// ===================================================================
// Kernel 4: collect candidates >= tau (unordered); also F/H factors
// ===================================================================
__global__ void collect_kernel() {
    const int j = blockIdx.x * 256 + threadIdx.x;
    const float v = g_adst[j];
    g_F[j] = __expf(v);
    g_H[j] = __expf(0.01f * v);
    if (v >= g_tau) {
        const int p = atomicAdd(&g_ccount, 1);
        if (p < 256) { g_cand[p] = j; g_candval[p] = v; }
    }
}

// ===================================================================
// Kernel 5: per-row factors from exact masked row-max over candidates
// ===================================================================
__global__ void rowprep_kernel(const int* __restrict__ adj) {
    __shared__ int   scand[256];
    __shared__ float scval[256];
    __shared__ int   scount;
    const int t = threadIdx.x;
    if (t == 0) { int c = g_ccount; scount = c < 256 ? c : 256; }
    scand[t] = g_cand[t];
    scval[t] = g_candval[t];
    __syncthreads();
    const int i = blockIdx.x * 256 + t;
    const float as = g_asrc[i];
    float rm = g_adst[i];                     // diag always accessible
    const int n = scount;
    const int* arow = adj + (size_t)i * NN;
#pragma unroll 8
    for (int c = 0; c < n; c++) {
        if (__ldg(&arow[scand[c]]) != 0) rm = fmaxf(rm, scval[c]);
    }
    const float sm = as + rm;
    if (sm > 0.f) {
        g_T[i] = -as;
        g_V[i] = __expf(-0.99f * as - rm);
        g_R[i] = __expf(-rm);
    } else {
        g_T[i] = 3e38f;
        g_V[i] = __expf(-0.01f * rm);
        g_R[i] = 0.f;
    }
}

// ===================================================================
// Kernel 6: fused pipelined P-construction + HMMA P@Xp
//   grid (64, JS); 256 threads / 8 warps; occ 1 (register-rich)
//   smem: Ps @0 (34816) | Bs[2] @34816 (2x34816) | sT/sV/sR @104448
// ===================================================================
#define BS_OFF   34816
#define ST_OFF   104448
#define SV_OFF   104960
#define SR_OFF   105472
#define SMEM_ATTN 105984

struct AdjRegs { int4 v[8]; };  // 4 rows x 2 int4 (32 j)

__device__ __forceinline__ void load_adj4(AdjRegs& r, const int4* __restrict__ adj4,
                                          size_t base4, int row0) {
#pragma unroll
    for (int rr = 0; rr < 4; rr++) {
        r.v[2 * rr]     = __ldcs(adj4 + base4 + (size_t)(row0 + rr) * (NN / 4));
        r.v[2 * rr + 1] = __ldcs(adj4 + base4 + (size_t)(row0 + rr) * (NN / 4) + 1);
    }
}

__device__ __forceinline__ void build4(const AdjRegs& r, int row0,
                                       const float* F, const float* H, const float* A,
                                       const float* sT, const float* sV, const float* sR,
                                       __half* Ps, float* lacc,
                                       int rqbase, int jq, int jj0, int i0) {
#pragma unroll
    for (int rr = 0; rr < 4; rr++) {
        const int row = rqbase + row0 + rr;
        const int i = i0 + row;
        const int* mk = (const int*)&r.v[2 * rr];
        const float T = sT[row], V = sV[row], R = sR[row];
        float p[8]; float ls = 0.f;
#pragma unroll
        for (int jj = 0; jj < 8; jj++) {
            float sel = (A[jj] > T) ? R * F[jj] : V * H[jj];
            sel = fminf(sel, 60000.f);
            const bool on = (mk[jj] != 0) || (jj0 + jj == i);
            p[jj] = on ? sel : 0.f;
            ls += p[jj];
        }
        lacc[row0 + rr] += ls;
        uint4 st;
        __half2 h;
        h = __floats2half2_rn(p[0], p[1]); st.x = *(uint32_t*)&h;
        h = __floats2half2_rn(p[2], p[3]); st.y = *(uint32_t*)&h;
        h = __floats2half2_rn(p[4], p[5]); st.z = *(uint32_t*)&h;
        h = __floats2half2_rn(p[6], p[7]); st.w = *(uint32_t*)&h;
        *(uint4*)(Ps + row * PSTR + jq * 8) = st;
    }
}

__device__ __forceinline__ void mma_tile(uint32_t ps_u, uint32_t bs_u,
                                         int wm, int wn, int lane,
                                         float acc[2][8][4]) {
    const int m0r = wm * 32;
    const int n0  = wn * 64;
#pragma unroll
    for (int ks = 0; ks < 8; ks++) {
        uint32_t a[2][4];
#pragma unroll
        for (int mt = 0; mt < 2; mt++) {
            const uint32_t addr = ps_u + 2 * ((m0r + mt * 16 + (lane & 15)) * PSTR
                                              + ks * 16 + (lane >> 4) * 8);
            LDSM4(a[mt], addr);
        }
#pragma unroll
        for (int nt = 0; nt < 4; nt++) {
            uint32_t b[4];
            const uint32_t addr = bs_u + 2 * ((n0 + nt * 16 + (lane & 7) + ((lane >> 4) << 3)) * PSTR
                                              + ks * 16 + ((lane >> 3) & 1) * 8);
            LDSM4(b, addr);
#pragma unroll
            for (int mt = 0; mt < 2; mt++) {
                MMA16816(acc[mt][nt * 2 + 0], a[mt], b[0], b[1]);
                MMA16816(acc[mt][nt * 2 + 1], a[mt], b[2], b[3]);
            }
        }
    }
}

__global__ void __launch_bounds__(256, 1)
attn_kernel(const int* __restrict__ adj) {
    extern __shared__ char smem[];
    __half* Ps  = (__half*)(smem);
    float*  sT  = (float*)(smem + ST_OFF);
    float*  sV  = (float*)(smem + SV_OFF);
    float*  sR  = (float*)(smem + SR_OFF);
    const uint32_t ps_u  = smem_u32(smem);
    const uint32_t bs_u0 = ps_u + BS_OFF;

    const int tid  = threadIdx.x;
    const int w    = tid >> 5;
    const int lane = tid & 31;
    const int rq   = tid >> 4;        // 16 row-groups of 8
    const int jq   = tid & 15;        // 16 j-groups of 8
    const int wm   = w & 3;
    const int wn   = w >> 2;
    const int i0    = blockIdx.x * 128;
    const int js    = blockIdx.y;
    const int jbase = js * JPB;

    if (tid < 128) {
        sT[tid] = g_T[i0 + tid];
        sV[tid] = g_V[i0 + tid];
        sR[tid] = g_R[i0 + tid];
    }
    float acc[2][8][4];
#pragma unroll
    for (int mt = 0; mt < 2; mt++)
#pragma unroll
        for (int nf = 0; nf < 8; nf++)
#pragma unroll
            for (int q = 0; q < 4; q++) acc[mt][nf][q] = 0.f;
    float lacc[8];
#pragma unroll
    for (int rr = 0; rr < 8; rr++) lacc[rr] = 0.f;

    const int4* adj4 = (const int4*)adj;
    const size_t brow = (size_t)(i0 + rq * 8) * (NN / 4) + (size_t)((jbase + jq * 8) >> 2);

    // issue B(t) into buffer t&1
    const __half* bsrc0 = g_XphT + (size_t)(tid >> 1) * NN + jbase + (tid & 1) * 64;
    const uint32_t bdst0 = bs_u0 + (uint32_t)(tid >> 1) * (PSTR * 2) + (uint32_t)(tid & 1) * 128;
#define ISSUE_B(t)                                                              \
    do {                                                                        \
        const char* _s = (const char*)(bsrc0 + (t) * 128);                      \
        const uint32_t _d = bdst0 + ((t) & 1) * PS_BYTES;                       \
        _Pragma("unroll")                                                       \
        for (int _it = 0; _it < 8; _it++) CP_ASYNC16(_d + _it * 16, _s + _it * 16); \
        CP_COMMIT();                                                            \
    } while (0)

    AdjRegs pfA, pfB, tmp;
    ISSUE_B(0);
    load_adj4(pfA, adj4, brow, 0);    // tile 0, rows 0-3

    float Fv[8], Hv[8], Av[8];
#define LOAD_FHA(t)                                                             \
    do {                                                                        \
        const int _j = jbase + (t) * 128 + jq * 8;                              \
        *(float4*)(Fv)     = __ldg((const float4*)(g_F + _j));                  \
        *(float4*)(Fv + 4) = __ldg((const float4*)(g_F + _j + 4));              \
        *(float4*)(Hv)     = __ldg((const float4*)(g_H + _j));                  \
        *(float4*)(Hv + 4) = __ldg((const float4*)(g_H + _j + 4));              \
        *(float4*)(Av)     = __ldg((const float4*)(g_adst + _j));               \
        *(float4*)(Av + 4) = __ldg((const float4*)(g_adst + _j + 4));           \
    } while (0)

#pragma unroll 1
    for (int tt = 0; tt < NT / 2; tt++) {
        const int t0 = 2 * tt, t1 = 2 * tt + 1;
        // ---------- tile t0 (even: P from pfA, prefetch into pfB) ----------
        CP_WAIT0();
        __syncthreads();                              // B(t0) visible; MMA(t0-1) done
        ISSUE_B(t1);
        load_adj4(tmp, adj4, brow + (size_t)(t0 * 32), 4);   // t0 rows 4-7
        load_adj4(pfB, adj4, brow + (size_t)(t1 * 32), 0);   // t1 rows 0-3
        LOAD_FHA(t0);
        {
            const int jj0 = jbase + t0 * 128 + jq * 8;
            build4(pfA, 0, Fv, Hv, Av, sT, sV, sR, Ps, lacc, rq * 8, jq, jj0, i0);
            build4(tmp, 4, Fv, Hv, Av, sT, sV, sR, Ps, lacc, rq * 8, jq, jj0, i0);
        }
        __syncthreads();                              // Ps ready
        mma_tile(ps_u, bs_u0 + (t0 & 1) * PS_BYTES, wm, wn, lane, acc);

        // ---------- tile t1 (odd: P from pfB, prefetch into pfA) ----------
        CP_WAIT0();
        __syncthreads();
        if (t1 + 1 < NT) ISSUE_B(t1 + 1);
        load_adj4(tmp, adj4, brow + (size_t)(t1 * 32), 4);   // t1 rows 4-7
        if (t1 + 1 < NT)
            load_adj4(pfA, adj4, brow + (size_t)((t1 + 1) * 32), 0);
        LOAD_FHA(t1);
        {
            const int jj0 = jbase + t1 * 128 + jq * 8;
            build4(pfB, 0, Fv, Hv, Av, sT, sV, sR, Ps, lacc, rq * 8, jq, jj0, i0);
            build4(tmp, 4, Fv, Hv, Av, sT, sV, sR, Ps, lacc, rq * 8, jq, jj0, i0);
        }
        __syncthreads();
        mma_tile(ps_u, bs_u0 + (t1 & 1) * PS_BYTES, wm, wn, lane, acc);
    }

    // ---- epilogue ----
    {
        float* dst = g_part + ((size_t)js * NN + i0) * FOUT;
        const int rbase = wm * 32 + (lane >> 2);
        const int cbase = wn * 64 + (lane & 3) * 2;
#pragma unroll
        for (int mt = 0; mt < 2; mt++) {
#pragma unroll
            for (int nf = 0; nf < 8; nf++) {
                const int r = rbase + mt * 16;
                const int c = cbase + nf * 8;
                *(float2*)(dst + (size_t)r * FOUT + c) =
                    make_float2(acc[mt][nf][0], acc[mt][nf][1]);
                *(float2*)(dst + (size_t)(r + 8) * FOUT + c) =
                    make_float2(acc[mt][nf][2], acc[mt][nf][3]);
            }
        }
    }
    // row sums: alias scratch into Bs buffer 0 (free: last MMA read buffer 1 & Ps)
    float* s_l = (float*)(smem + BS_OFF);
#pragma unroll
    for (int rr = 0; rr < 8; rr++) s_l[(rq * 8 + rr) * 16 + jq] = lacc[rr];
    __syncthreads();
    if (tid < 128) {
        float L = 0.f;
#pragma unroll
        for (int q = 0; q < 16; q++) L += s_l[tid * 16 + q];
        g_lpart[js * NN + i0 + tid] = L;
    }
}

// ===================================================================
// Kernel 7: combine partials, divide, sigmoid
// ===================================================================
__global__ void combine_kernel(float* __restrict__ out) {
    const int gid = blockIdx.x * 256 + threadIdx.x;
    const int i = gid >> 5;
    const int c = gid & 31;
    float4 s = make_float4(0.f, 0.f, 0.f, 0.f);
    float L = 0.f;
#pragma unroll
    for (int js = 0; js < JS; js++) {
        const float4 a = *(const float4*)(g_part + ((size_t)js * NN + i) * FOUT + c * 4);
        s.x += a.x; s.y += a.y; s.z += a.z; s.w += a.w;
        L += g_lpart[js * NN + i];
    }
    const float inv = 1.f / L;
    float4 o;
    o.x = 1.f / (1.f + __expf(-s.x * inv));
    o.y = 1.f / (1.f + __expf(-s.y * inv));
    o.z = 1.f / (1.f + __expf(-s.z * inv));
    o.w = 1.f / (1.f + __expf(-s.w * inv));
    *(float4*)(out + (size_t)i * FOUT + c * 4) = o;
}

// ===================================================================
extern "C" void kernel_launch(void* const* d_in, const int* in_sizes, int n_in,
                              void* d_out, int out_size) {
    const float* X   = (const float*)d_in[0];
    const int*   adj = (const int*)  d_in[1];
    const float* W   = (const float*)d_in[2];
    const float* b   = (const float*)d_in[3];
    const float* S   = (const float*)d_in[4];
    float* out = (float*)d_out;

    gemm_xp_kernel<<<dim3(FOUT / 64, NN / 64), dim3(16, 16)>>>(X, W, b);
    proj_kernel<<<(NN * 32) / 256, 256>>>(S);
    hist_kernel<<<1, 1024>>>();
    collect_kernel<<<NN / 256, 256>>>();
    rowprep_kernel<<<NN / 256, 256>>>(adj);

    cudaFuncSetAttribute(attn_kernel, cudaFuncAttributeMaxDynamicSharedMemorySize, SMEM_ATTN);
    attn_kernel<<<dim3(NN / 128, JS), 256, SMEM_ATTN>>>(adj);
    combine_kernel<<<(NN * 32) / 256, 256>>>(out);
}

// round 6
// speedup vs baseline: 4.0730x; 1.1736x over previous
#include <cuda_runtime.h>
#include <cuda_fp16.h>
#include <math.h>
#include <stdint.h>

#define NN    8192
#define FIN   256
#define FOUT  128
#define JS    2
#define JPB   (NN / JS)          // 4096
#define NT    (JPB / 128)        // 32
#define PSTR  136
#define PTILE (128 * PSTR * 2)   // 34816
#define ADJSTR 132               // ints per adj smem row (528 B)
#define ABUF  (128 * ADJSTR * 4) // 67584

__device__ float   g_Xp[NN * FOUT];
__device__ __half  g_XphT[(size_t)FOUT * NN];
__device__ float   g_asrc[NN], g_adst[NN];
__device__ float   g_F[NN], g_H[NN];
__device__ int     g_cand[256];
__device__ float   g_candval[256];
__device__ int     g_ccount;
__device__ float   g_part[(size_t)JS * NN * FOUT];
__device__ float   g_lpart[JS * NN];

__device__ __forceinline__ uint32_t smem_u32(const void* p) {
    uint32_t a;
    asm("{ .reg .u64 t; cvta.to.shared.u64 t, %1; cvt.u32.u64 %0, t; }" : "=r"(a) : "l"(p));
    return a;
}
#define LDSM4(r, addr)                                                           \
    asm volatile("ldmatrix.sync.aligned.m8n8.x4.shared.b16 {%0,%1,%2,%3}, [%4];" \
        : "=r"((r)[0]), "=r"((r)[1]), "=r"((r)[2]), "=r"((r)[3]) : "r"(addr))
#define MMA16816(d, a, b0, b1)                                                   \
    asm volatile("mma.sync.aligned.m16n8k16.row.col.f32.f16.f16.f32 "            \
        "{%0,%1,%2,%3},{%4,%5,%6,%7},{%8,%9},{%0,%1,%2,%3};"                     \
        : "+f"((d)[0]), "+f"((d)[1]), "+f"((d)[2]), "+f"((d)[3])                 \
        : "r"((a)[0]), "r"((a)[1]), "r"((a)[2]), "r"((a)[3]), "r"(b0), "r"(b1))
#define CP_ASYNC16(dst, src) \
    asm volatile("cp.async.cg.shared.global [%0], [%1], 16;" :: "r"(dst), "l"(src))
#define CP_COMMIT() asm volatile("cp.async.commit_group;" ::: "memory")
#define CP_WAIT0()  asm volatile("cp.async.wait_group 0;" ::: "memory")
#define MBARRIER_INIT(mb, cnt) \
    asm volatile("mbarrier.init.shared.b64 [%0], %1;" :: "r"(mb), "r"(cnt) : "memory")
#define MBARRIER_EXPECT_TX(mb, bytes) \
    asm volatile("mbarrier.arrive.expect_tx.shared.b64 _, [%0], %1;" :: "r"(mb), "r"(bytes) : "memory")
#define MBARRIER_WAIT_PARITY(mb, ph) do {                                            \
    uint32_t _m = (mb), _p = (ph), _d;                                               \
    asm volatile("{\n\t.reg .pred p;\n\t"                                            \
        "mbarrier.try_wait.parity.acquire.cta.shared::cta.b64 p, [%1], %2;\n\t"      \
        "selp.b32 %0, 1, 0, p;\n\t}" : "=r"(_d) : "r"(_m), "r"(_p) : "memory");      \
    if (!_d) {                                                                       \
        asm volatile("{\n\t.reg .pred P1;\n\t"                                       \
            "WL%=:\n\t"                                                              \
            "mbarrier.try_wait.parity.acquire.cta.shared::cta.b64 P1, [%0], %1, 0x989680;\n\t" \
            "@P1 bra.uni WD%=;\n\t bra.uni WL%=;\n\t WD%=:\n\t}"                     \
            :: "r"(_m), "r"(_p) : "memory");                                         \
    }                                                                                \
} while (0)
#define BULK_G2S(dst, src, bytes, mb)                                                 \
    asm volatile("cp.async.bulk.shared::cluster.global.mbarrier::complete_tx::bytes " \
        "[%0], [%1], %2, [%3];" :: "r"(dst), "l"(src), "r"(bytes), "r"(mb) : "memory")

// ================= Kernel 1: Xp = X W^T + b (+fp16 transpose) =================
__global__ void gemm_xp_kernel(const float* __restrict__ X,
                               const float* __restrict__ W,
                               const float* __restrict__ b) {
    __shared__ float Xs[64][17];
    __shared__ float Ws[64][17];
    const int tx = threadIdx.x, ty = threadIdx.y;
    const int tid = ty * 16 + tx;
    const int row0 = blockIdx.y * 64, col0 = blockIdx.x * 64;
    const int lr = tid >> 2, lk = (tid & 3) * 4;
    float acc[4][4];
#pragma unroll
    for (int i = 0; i < 4; i++)
#pragma unroll
        for (int j = 0; j < 4; j++) acc[i][j] = 0.f;
    for (int kt = 0; kt < FIN; kt += 16) {
        float4 xv = *reinterpret_cast<const float4*>(&X[(row0 + lr) * FIN + kt + lk]);
        Xs[lr][lk + 0] = xv.x; Xs[lr][lk + 1] = xv.y;
        Xs[lr][lk + 2] = xv.z; Xs[lr][lk + 3] = xv.w;
        float4 wv = *reinterpret_cast<const float4*>(&W[(col0 + lr) * FIN + kt + lk]);
        Ws[lr][lk + 0] = wv.x; Ws[lr][lk + 1] = wv.y;
        Ws[lr][lk + 2] = wv.z; Ws[lr][lk + 3] = wv.w;
        __syncthreads();
#pragma unroll
        for (int k = 0; k < 16; ++k) {
            float a[4], w[4];
#pragma unroll
            for (int i = 0; i < 4; i++) a[i] = Xs[ty * 4 + i][k];
#pragma unroll
            for (int j = 0; j < 4; j++) w[j] = Ws[tx * 4 + j][k];
#pragma unroll
            for (int i = 0; i < 4; i++)
#pragma unroll
                for (int j = 0; j < 4; j++) acc[i][j] += a[i] * w[j];
        }
        __syncthreads();
    }
#pragma unroll
    for (int i = 0; i < 4; i++) {
        const int row = row0 + ty * 4 + i;
#pragma unroll
        for (int j = 0; j < 4; j++) {
            const int f = col0 + tx * 4 + j;
            const float v = acc[i][j] + b[f];
            g_Xp[row * FOUT + f] = v;
            g_XphT[(size_t)f * NN + row] = __float2half(v);
        }
    }
}

// ================= Kernel 2: projections + per-j exp factors =================
__global__ void proj_kernel(const float* __restrict__ S) {
    int gw   = (blockIdx.x * blockDim.x + threadIdx.x) >> 5;
    int lane = threadIdx.x & 31;
    if (gw >= NN) return;
    const float4 x  = *((const float4*)(g_Xp + gw * FOUT) + lane);
    const float4 s1 = *((const float4*)(S) + lane);
    const float4 s2 = *((const float4*)(S + FOUT) + lane);
    float ss = x.x * s1.x + x.y * s1.y + x.z * s1.z + x.w * s1.w;
    float sd = x.x * s2.x + x.y * s2.y + x.z * s2.z + x.w * s2.w;
#pragma unroll
    for (int o = 16; o > 0; o >>= 1) {
        ss += __shfl_down_sync(0xffffffffu, ss, o);
        sd += __shfl_down_sync(0xffffffffu, sd, o);
    }
    if (lane == 0) {
        g_asrc[gw] = ss; g_adst[gw] = sd;
        g_F[gw] = __expf(sd); g_H[gw] = __expf(0.01f * sd);
    }
}

// ====== Kernel 3: single block: max, histogram->tau, collect candidates ======
__global__ void histcollect_kernel() {
    __shared__ float red[32];
    __shared__ int   hist[128];
    __shared__ float smx, stau;
    const int t = threadIdx.x;  // 1024
    float m = -3e38f;
    for (int i = t; i < NN; i += 1024) m = fmaxf(m, g_adst[i]);
#pragma unroll
    for (int o = 16; o > 0; o >>= 1) m = fmaxf(m, __shfl_down_sync(0xffffffffu, m, o));
    if ((t & 31) == 0) red[t >> 5] = m;
    if (t < 128) hist[t] = 0;
    __syncthreads();
    if (t < 32) {
        float v = red[t];
#pragma unroll
        for (int o = 16; o > 0; o >>= 1) v = fmaxf(v, __shfl_down_sync(0xffffffffu, v, o));
        if (t == 0) smx = v;
    }
    __syncthreads();
    const float mx = smx;
    for (int i = t; i < NN; i += 1024) {
        const float v = g_adst[i];
        if (v >= mx - 20.f) {
            int bin = (int)((mx - v) * (128.f / 20.f));
            bin = bin < 127 ? bin : 127;
            atomicAdd(&hist[bin], 1);
        }
    }
    __syncthreads();
    if (t == 0) {
        int cum = 0;
        float tau = mx - 20.f;
        for (int b2 = 0; b2 < 128; b2++) {
            cum += hist[b2];
            if (cum >= 96) { tau = mx - (float)(b2 + 1) * (20.f / 128.f); break; }
        }
        stau = tau; g_ccount = 0;
    }
    __syncthreads();
    const float tau = stau;
    for (int i = t; i < NN; i += 1024) {
        const float v = g_adst[i];
        if (v >= tau) {
            const int p = atomicAdd(&g_ccount, 1);
            if (p < 256) { g_cand[p] = i; g_candval[p] = v; }
        }
    }
}

// ================= Kernel 4: bulk-copy pipelined attention =================
#define SM_P    0
#define SM_B    34816
#define SM_ADJ  69632
#define SM_C1   204800
#define SM_C2   205312
#define SM_CAND 205824
#define SM_CVAL 206848
#define SM_MB   207872
#define SM_NC   207888
#define SMEM_ATTN 207904

__global__ void __launch_bounds__(256, 1)
attn_kernel(const int* __restrict__ adj) {
    extern __shared__ char smem[];
    const uint32_t su = smem_u32(smem);
    __half* Ps   = (__half*)(smem + SM_P);
    float*  sC1  = (float*)(smem + SM_C1);
    float*  sC2  = (float*)(smem + SM_C2);
    int*    scand = (int*)(smem + SM_CAND);
    float*  scval = (float*)(smem + SM_CVAL);
    int*    sNC  = (int*)(smem + SM_NC);
    const uint32_t ps_u = su + SM_P, bs_u = su + SM_B, adj_u = su + SM_ADJ;
    const uint32_t mb[2] = { su + SM_MB, su + SM_MB + 8 };

    const int tid  = threadIdx.x;
    const int w    = tid >> 5;
    const int lane = tid & 31;
    const int rq   = tid >> 4;     // 8 rows each
    const int jq   = tid & 15;     // 8 j each
    const int wm   = w & 3, wn = w >> 2;
    const int i0    = blockIdx.x * 128;
    const int js    = blockIdx.y;
    const int jbase = js * JPB;

    // ---- prologue: row factors C1/C2 (masked row-max over candidates) ----
    scand[tid] = g_cand[tid];
    scval[tid] = g_candval[tid];
    if (tid == 0) {
        int c = g_ccount; sNC[0] = c < 256 ? c : 256;
        MBARRIER_INIT(mb[0], 1); MBARRIER_INIT(mb[1], 1);
    }
    __syncthreads();
    {
        float* stmp = (float*)(smem + SM_B);   // B buffer unused yet
        const int nc = sNC[0];
        const int row = tid >> 1;
        const int i = i0 + row;
        float rm = ((tid & 1) == 0) ? __ldg(&g_adst[i]) : -3e38f;
        const int* arow = adj + (size_t)i * NN;
#pragma unroll 4
        for (int c = (tid & 1); c < nc; c += 2)
            if (__ldg(&arow[scand[c]]) != 0) rm = fmaxf(rm, scval[c]);
        stmp[tid] = rm;
        __syncthreads();
        if (tid < 128) {
            const float r2 = fmaxf(stmp[2 * tid], stmp[2 * tid + 1]);
            const float as = __ldg(&g_asrc[i0 + tid]);
            const float s = as + r2;
            const float m = fmaxf(s, 0.01f * s);
            sC1[tid] = __expf(as - m);
            sC2[tid] = __expf(0.01f * as - m);
        }
        __syncthreads();
    }
    float C1r[8], C2r[8], lacc[8];
#pragma unroll
    for (int rr = 0; rr < 8; rr++) {
        C1r[rr] = sC1[rq * 8 + rr];
        C2r[rr] = sC2[rq * 8 + rr];
        lacc[rr] = 0.f;
    }
    float acc[2][8][4];
#pragma unroll
    for (int mt = 0; mt < 2; mt++)
#pragma unroll
        for (int nf = 0; nf < 8; nf++)
#pragma unroll
            for (int q = 0; q < 4; q++) acc[mt][nf][q] = 0.f;

    // ---- pre-issue adj(0), adj(1) ----
    if (tid == 0) MBARRIER_EXPECT_TX(mb[0], 65536);
    if (tid < 128)
        BULK_G2S(adj_u + (uint32_t)tid * (ADJSTR * 4),
                 (const void*)(adj + (size_t)(i0 + tid) * NN + jbase), 512, mb[0]);
    if (tid == 0) MBARRIER_EXPECT_TX(mb[1], 65536);
    if (tid < 128)
        BULK_G2S(adj_u + ABUF + (uint32_t)tid * (ADJSTR * 4),
                 (const void*)(adj + (size_t)(i0 + tid) * NN + jbase + 128), 512, mb[1]);

    const __half* bsrc0 = g_XphT + (size_t)(tid >> 1) * NN + jbase + (tid & 1) * 64;
    const uint32_t bdst0 = bs_u + (uint32_t)(tid >> 1) * (PSTR * 2) + (uint32_t)(tid & 1) * 128;

#pragma unroll 1
    for (int t = 0; t < NT; t++) {
        const int s = t & 1;
        MBARRIER_WAIT_PARITY(mb[s], (t >> 1) & 1);
        // B(t) via cp.async (single buffer; prev MMA finished at loop-end sync)
        {
            const char* bs2 = (const char*)(bsrc0 + t * 128);
#pragma unroll
            for (int it = 0; it < 8; it++) CP_ASYNC16(bdst0 + it * 16, bs2 + it * 16);
            CP_COMMIT();
        }
        // per-j factors
        float Fv[8], Hv[8];
        {
            const int jj = jbase + t * 128 + jq * 8;
            *(float4*)(Fv)     = __ldg((const float4*)(g_F + jj));
            *(float4*)(Fv + 4) = __ldg((const float4*)(g_F + jj + 4));
            *(float4*)(Hv)     = __ldg((const float4*)(g_H + jj));
            *(float4*)(Hv + 4) = __ldg((const float4*)(g_H + jj + 4));
        }
        // build P(t) from smem adj
        {
            const int* As = (const int*)(smem + SM_ADJ + s * ABUF);
            const int jj0 = jbase + t * 128 + jq * 8;
#pragma unroll
            for (int rr = 0; rr < 8; rr++) {
                const int row = rq * 8 + rr;
                const int i = i0 + row;
                const int4 a0 = *(const int4*)(As + row * ADJSTR + jq * 8);
                const int4 a1 = *(const int4*)(As + row * ADJSTR + jq * 8 + 4);
                const int mk[8] = { a0.x, a0.y, a0.z, a0.w, a1.x, a1.y, a1.z, a1.w };
                const float C1 = C1r[rr], C2 = C2r[rr];
                float p[8]; float ls = 0.f;
#pragma unroll
                for (int jj = 0; jj < 8; jj++) {
                    const float sel = fminf(fmaxf(C1 * Fv[jj], C2 * Hv[jj]), 60000.f);
                    const bool on = (mk[jj] != 0) || (jj0 + jj == i);
                    p[jj] = on ? sel : 0.f;
                    ls += p[jj];
                }
                lacc[rr] += ls;
                uint4 st;
                __half2 h;
                h = __floats2half2_rn(p[0], p[1]); st.x = *(uint32_t*)&h;
                h = __floats2half2_rn(p[2], p[3]); st.y = *(uint32_t*)&h;
                h = __floats2half2_rn(p[4], p[5]); st.z = *(uint32_t*)&h;
                h = __floats2half2_rn(p[6], p[7]); st.w = *(uint32_t*)&h;
                *(uint4*)(Ps + row * PSTR + jq * 8) = st;
            }
        }
        CP_WAIT0();
        __syncthreads();                 // P,B visible; adjS[s] fully consumed
        if (t + 2 < NT) {                // refill buffer s while MMA runs
            if (tid == 0) MBARRIER_EXPECT_TX(mb[s], 65536);
            if (tid < 128)
                BULK_G2S(adj_u + (uint32_t)s * ABUF + (uint32_t)tid * (ADJSTR * 4),
                         (const void*)(adj + (size_t)(i0 + tid) * NN + jbase + (t + 2) * 128),
                         512, mb[s]);
        }
        // MMA(t)
        {
            const int m0r = wm * 32, n0 = wn * 64;
#pragma unroll
            for (int ks = 0; ks < 8; ks++) {
                uint32_t a[2][4];
#pragma unroll
                for (int mt = 0; mt < 2; mt++) {
                    const uint32_t addr = ps_u + 2 * ((m0r + mt * 16 + (lane & 15)) * PSTR
                                                      + ks * 16 + (lane >> 4) * 8);
                    LDSM4(a[mt], addr);
                }
#pragma unroll
                for (int nt = 0; nt < 4; nt++) {
                    uint32_t bf[4];
                    const uint32_t addr = bs_u + 2 * ((n0 + nt * 16 + (lane & 7) + ((lane >> 4) << 3)) * PSTR
                                                      + ks * 16 + ((lane >> 3) & 1) * 8);
                    LDSM4(bf, addr);
#pragma unroll
                    for (int mt = 0; mt < 2; mt++) {
                        MMA16816(acc[mt][nt * 2 + 0], a[mt], bf[0], bf[1]);
                        MMA16816(acc[mt][nt * 2 + 1], a[mt], bf[2], bf[3]);
                    }
                }
            }
        }
        __syncthreads();                 // MMA done before next overwrite of P/B
    }

    // ---- epilogue ----
    {
        float* dst = g_part + ((size_t)js * NN + i0) * FOUT;
        const int rbase = wm * 32 + (lane >> 2);
        const int cbase = wn * 64 + (lane & 3) * 2;
#pragma unroll
        for (int mt = 0; mt < 2; mt++) {
#pragma unroll
            for (int nf = 0; nf < 8; nf++) {
                const int r = rbase + mt * 16;
                const int c = cbase + nf * 8;
                *(float2*)(dst + (size_t)r * FOUT + c) =
                    make_float2(acc[mt][nf][0], acc[mt][nf][1]);
                *(float2*)(dst + (size_t)(r + 8) * FOUT + c) =
                    make_float2(acc[mt][nf][2], acc[mt][nf][3]);
            }
        }
    }
    float* s_l = (float*)(smem + SM_B);
#pragma unroll
    for (int rr = 0; rr < 8; rr++) s_l[(rq * 8 + rr) * 16 + jq] = lacc[rr];
    __syncthreads();
    if (tid < 128) {
        float L = 0.f;
#pragma unroll
        for (int q = 0; q < 16; q++) L += s_l[tid * 16 + q];
        g_lpart[js * NN + i0 + tid] = L;
    }
}

// ================= Kernel 5: combine + sigmoid =================
__global__ void combine_kernel(float* __restrict__ out) {
    const int gid = blockIdx.x * 256 + threadIdx.x;
    const int i = gid >> 5;
    const int c = gid & 31;
    float4 s = make_float4(0.f, 0.f, 0.f, 0.f);
    float L = 0.f;
#pragma unroll
    for (int js = 0; js < JS; js++) {
        const float4 a = *(const float4*)(g_part + ((size_t)js * NN + i) * FOUT + c * 4);
        s.x += a.x; s.y += a.y; s.z += a.z; s.w += a.w;
        L += g_lpart[js * NN + i];
    }
    const float inv = 1.f / L;
    float4 o;
    o.x = 1.f / (1.f + __expf(-s.x * inv));
    o.y = 1.f / (1.f + __expf(-s.y * inv));
    o.z = 1.f / (1.f + __expf(-s.z * inv));
    o.w = 1.f / (1.f + __expf(-s.w * inv));
    *(float4*)(out + (size_t)i * FOUT + c * 4) = o;
}

extern "C" void kernel_launch(void* const* d_in, const int* in_sizes, int n_in,
                              void* d_out, int out_size) {
    const float* X   = (const float*)d_in[0];
    const int*   adj = (const int*)  d_in[1];
    const float* W   = (const float*)d_in[2];
    const float* b   = (const float*)d_in[3];
    const float* S   = (const float*)d_in[4];
    float* out = (float*)d_out;

    gemm_xp_kernel<<<dim3(FOUT / 64, NN / 64), dim3(16, 16)>>>(X, W, b);
    proj_kernel<<<(NN * 32) / 256, 256>>>(S);
    histcollect_kernel<<<1, 1024>>>();

    cudaFuncSetAttribute(attn_kernel, cudaFuncAttributeMaxDynamicSharedMemorySize, SMEM_ATTN);
    attn_kernel<<<dim3(NN / 128, JS), 256, SMEM_ATTN>>>(adj);
    combine_kernel<<<(NN * 32) / 256, 256>>>(out);
}

// round 7
// speedup vs baseline: 5.6385x; 1.3844x over previous
#include <cuda_runtime.h>
#include <cuda_fp16.h>
#include <math.h>
#include <stdint.h>

#define NN    8192
#define FIN   256
#define FOUT  128
#define JS    2
#define JPB   (NN / JS)          // 4096
#define NT    (JPB / 128)        // 32
#define PSTR  136
#define PTILE (128 * PSTR * 2)   // 34816
#define ADJSTR 132               // ints per adj smem row (528 B)

__device__ float   g_Xp[NN * FOUT];
__device__ __half  g_XphT[(size_t)FOUT * NN];
__device__ float   g_asrc[NN], g_adst[NN];
__device__ float   g_F[NN], g_H[NN];
__device__ float   g_max[1];
__device__ float   g_part[(size_t)JS * NN * FOUT];
__device__ float   g_lpart[JS * NN];

__device__ __forceinline__ uint32_t smem_u32(const void* p) {
    uint32_t a;
    asm("{ .reg .u64 t; cvta.to.shared.u64 t, %1; cvt.u32.u64 %0, t; }" : "=r"(a) : "l"(p));
    return a;
}
#define LDSM4(r, addr)                                                           \
    asm volatile("ldmatrix.sync.aligned.m8n8.x4.shared.b16 {%0,%1,%2,%3}, [%4];" \
        : "=r"((r)[0]), "=r"((r)[1]), "=r"((r)[2]), "=r"((r)[3]) : "r"(addr))
#define MMA16816(d, a, b0, b1)                                                   \
    asm volatile("mma.sync.aligned.m16n8k16.row.col.f32.f16.f16.f32 "            \
        "{%0,%1,%2,%3},{%4,%5,%6,%7},{%8,%9},{%0,%1,%2,%3};"                     \
        : "+f"((d)[0]), "+f"((d)[1]), "+f"((d)[2]), "+f"((d)[3])                 \
        : "r"((a)[0]), "r"((a)[1]), "r"((a)[2]), "r"((a)[3]), "r"(b0), "r"(b1))
#define CP_ASYNC16(dst, src) \
    asm volatile("cp.async.cg.shared.global [%0], [%1], 16;" :: "r"(dst), "l"(src))
#define CP_COMMIT() asm volatile("cp.async.commit_group;" ::: "memory")
#define CP_WAIT0()  asm volatile("cp.async.wait_group 0;" ::: "memory")
#define MBARRIER_INIT(mb, cnt) \
    asm volatile("mbarrier.init.shared.b64 [%0], %1;" :: "r"(mb), "r"(cnt) : "memory")
#define MBARRIER_EXPECT_TX(mb, bytes) \
    asm volatile("mbarrier.arrive.expect_tx.shared.b64 _, [%0], %1;" :: "r"(mb), "r"(bytes) : "memory")
#define MBARRIER_WAIT_PARITY(mb, ph) do {                                            \
    uint32_t _m = (mb), _p = (ph), _d;                                               \
    asm volatile("{\n\t.reg .pred p;\n\t"                                            \
        "mbarrier.try_wait.parity.acquire.cta.shared::cta.b64 p, [%1], %2;\n\t"      \
        "selp.b32 %0, 1, 0, p;\n\t}" : "=r"(_d) : "r"(_m), "r"(_p) : "memory");      \
    if (!_d) {                                                                       \
        asm volatile("{\n\t.reg .pred P1;\n\t"                                       \
            "WL%=:\n\t"                                                              \
            "mbarrier.try_wait.parity.acquire.cta.shared::cta.b64 P1, [%0], %1, 0x989680;\n\t" \
            "@P1 bra.uni WD%=;\n\t bra.uni WL%=;\n\t WD%=:\n\t}"                     \
            :: "r"(_m), "r"(_p) : "memory");                                         \
    }                                                                                \
} while (0)
#define BULK_G2S(dst, src, bytes, mb)                                                 \
    asm volatile("cp.async.bulk.shared::cluster.global.mbarrier::complete_tx::bytes " \
        "[%0], [%1], %2, [%3];" :: "r"(dst), "l"(src), "r"(bytes), "r"(mb) : "memory")

// ================= Kernel 1: Xp = X W^T + b (+fp16 transpose) =================
__global__ void gemm_xp_kernel(const float* __restrict__ X,
                               const float* __restrict__ W,
                               const float* __restrict__ b) {
    __shared__ float Xs[64][17];
    __shared__ float Ws[64][17];
    const int tx = threadIdx.x, ty = threadIdx.y;
    const int tid = ty * 16 + tx;
    const int row0 = blockIdx.y * 64, col0 = blockIdx.x * 64;
    const int lr = tid >> 2, lk = (tid & 3) * 4;
    float acc[4][4];
#pragma unroll
    for (int i = 0; i < 4; i++)
#pragma unroll
        for (int j = 0; j < 4; j++) acc[i][j] = 0.f;
    for (int kt = 0; kt < FIN; kt += 16) {
        float4 xv = *reinterpret_cast<const float4*>(&X[(row0 + lr) * FIN + kt + lk]);
        Xs[lr][lk + 0] = xv.x; Xs[lr][lk + 1] = xv.y;
        Xs[lr][lk + 2] = xv.z; Xs[lr][lk + 3] = xv.w;
        float4 wv = *reinterpret_cast<const float4*>(&W[(col0 + lr) * FIN + kt + lk]);
        Ws[lr][lk + 0] = wv.x; Ws[lr][lk + 1] = wv.y;
        Ws[lr][lk + 2] = wv.z; Ws[lr][lk + 3] = wv.w;
        __syncthreads();
#pragma unroll
        for (int k = 0; k < 16; ++k) {
            float a[4], w[4];
#pragma unroll
            for (int i = 0; i < 4; i++) a[i] = Xs[ty * 4 + i][k];
#pragma unroll
            for (int j = 0; j < 4; j++) w[j] = Ws[tx * 4 + j][k];
#pragma unroll
            for (int i = 0; i < 4; i++)
#pragma unroll
                for (int j = 0; j < 4; j++) acc[i][j] += a[i] * w[j];
        }
        __syncthreads();
    }
#pragma unroll
    for (int i = 0; i < 4; i++) {
        const int row = row0 + ty * 4 + i;
#pragma unroll
        for (int j = 0; j < 4; j++) {
            const int f = col0 + tx * 4 + j;
            const float v = acc[i][j] + b[f];
            g_Xp[row * FOUT + f] = v;
            g_XphT[(size_t)f * NN + row] = __float2half(v);
        }
    }
}

// ================= Kernel 2: projections + per-j exp factors =================
__global__ void proj_kernel(const float* __restrict__ S) {
    int gw   = (blockIdx.x * blockDim.x + threadIdx.x) >> 5;
    int lane = threadIdx.x & 31;
    if (gw >= NN) return;
    const float4 x  = *((const float4*)(g_Xp + gw * FOUT) + lane);
    const float4 s1 = *((const float4*)(S) + lane);
    const float4 s2 = *((const float4*)(S + FOUT) + lane);
    float ss = x.x * s1.x + x.y * s1.y + x.z * s1.z + x.w * s1.w;
    float sd = x.x * s2.x + x.y * s2.y + x.z * s2.z + x.w * s2.w;
#pragma unroll
    for (int o = 16; o > 0; o >>= 1) {
        ss += __shfl_down_sync(0xffffffffu, ss, o);
        sd += __shfl_down_sync(0xffffffffu, sd, o);
    }
    if (lane == 0) {
        g_asrc[gw] = ss; g_adst[gw] = sd;
        g_F[gw] = __expf(sd); g_H[gw] = __expf(0.01f * sd);
    }
}

// ================= Kernel 3: global max of a_dst =================
__global__ void maxred_kernel() {
    __shared__ float red[32];
    const int t = threadIdx.x;  // 1024
    float m = -3e38f;
    for (int i = t; i < NN; i += 1024) m = fmaxf(m, g_adst[i]);
#pragma unroll
    for (int o = 16; o > 0; o >>= 1) m = fmaxf(m, __shfl_down_sync(0xffffffffu, m, o));
    if ((t & 31) == 0) red[t >> 5] = m;
    __syncthreads();
    if (t < 32) {
        float v = red[t];
#pragma unroll
        for (int o = 16; o > 0; o >>= 1) v = fmaxf(v, __shfl_down_sync(0xffffffffu, v, o));
        if (t == 0) g_max[0] = v;
    }
}

// ================= Kernel 4: pipelined attention (double P/B, single adj) =====
#define SM_P    0
#define SM_B    69632
#define SM_ADJ  139264
#define SM_C1   206848
#define SM_C2   207360
#define SM_MB   207872
#define SMEM_ATTN 207904

__global__ void __launch_bounds__(256, 1)
attn_kernel(const int* __restrict__ adj) {
    extern __shared__ char smem[];
    const uint32_t su = smem_u32(smem);
    float* sC1 = (float*)(smem + SM_C1);
    float* sC2 = (float*)(smem + SM_C2);
    const uint32_t ps_u = su + SM_P, bs_u = su + SM_B, adj_u = su + SM_ADJ;
    const uint32_t mb = su + SM_MB;

    const int tid  = threadIdx.x;
    const int w    = tid >> 5;
    const int lane = tid & 31;
    const int rq   = tid >> 4;     // 16 row-groups of 8
    const int jq   = tid & 15;     // 16 j-groups of 8
    const int wm   = w & 3, wn = w >> 2;
    const int i0    = blockIdx.x * 128;
    const int js    = blockIdx.y;
    const int jbase = js * JPB;

    // ---- prologue: per-row C1/C2 from global-max shift ----
    if (tid < 128) {
        const float as = __ldg(&g_asrc[i0 + tid]);
        const float s  = as + __ldg(&g_max[0]);
        const float m  = fmaxf(s, 0.01f * s);      // lrelu upper bound of row max
        sC1[tid] = __expf(as - m);
        sC2[tid] = __expf(0.01f * as - m);
    }
    if (tid == 0) MBARRIER_INIT(mb, 1);
    __syncthreads();

    // ---- pre-issue adj(0) bulk + B(0) cp.async ----
    if (tid == 0) MBARRIER_EXPECT_TX(mb, 65536);
    if (tid < 128)
        BULK_G2S(adj_u + (uint32_t)tid * (ADJSTR * 4),
                 (const void*)(adj + (size_t)(i0 + tid) * NN + jbase), 512, mb);
    const __half* bsrc0 = g_XphT + (size_t)(tid >> 1) * NN + jbase + (tid & 1) * 64;
    const uint32_t bhalf = (uint32_t)(tid >> 1) * (PSTR * 2) + (uint32_t)(tid & 1) * 128;
    {
        const char* s0 = (const char*)bsrc0;
#pragma unroll
        for (int it = 0; it < 8; it++) CP_ASYNC16(bs_u + bhalf + it * 16, s0 + it * 16);
        CP_COMMIT();
    }

    float C1r[8], C2r[8], lacc[8];
#pragma unroll
    for (int rr = 0; rr < 8; rr++) {
        C1r[rr] = sC1[rq * 8 + rr];
        C2r[rr] = sC2[rq * 8 + rr];
        lacc[rr] = 0.f;
    }
    float acc[2][8][4];
#pragma unroll
    for (int mt = 0; mt < 2; mt++)
#pragma unroll
        for (int nf = 0; nf < 8; nf++)
#pragma unroll
            for (int q = 0; q < 4; q++) acc[mt][nf][q] = 0.f;

#pragma unroll 1
    for (int t = 0; t < NT; t++) {
        const int s = t & 1;
        // per-j factors (in flight while waiting adj)
        float Fv[8], Hv[8];
        {
            const int jj = jbase + t * 128 + jq * 8;
            *(float4*)(Fv)     = __ldg((const float4*)(g_F + jj));
            *(float4*)(Fv + 4) = __ldg((const float4*)(g_F + jj + 4));
            *(float4*)(Hv)     = __ldg((const float4*)(g_H + jj));
            *(float4*)(Hv + 4) = __ldg((const float4*)(g_H + jj + 4));
        }
        MBARRIER_WAIT_PARITY(mb, t & 1);
        // ---- build P(t) into P[s] ----
        {
            __half* Pt = (__half*)(smem + SM_P + s * PTILE);
            const int* As = (const int*)(smem + SM_ADJ);
            const int jj0 = jbase + t * 128 + jq * 8;
#pragma unroll
            for (int rr = 0; rr < 8; rr++) {
                const int row = rq * 8 + rr;
                const int i = i0 + row;
                const int4 a0 = *(const int4*)(As + row * ADJSTR + jq * 8);
                const int4 a1 = *(const int4*)(As + row * ADJSTR + jq * 8 + 4);
                const int mk[8] = { a0.x, a0.y, a0.z, a0.w, a1.x, a1.y, a1.z, a1.w };
                const float C1 = C1r[rr], C2 = C2r[rr];
                float p[8]; float ls = 0.f;
#pragma unroll
                for (int jj = 0; jj < 8; jj++) {
                    const float sel = fmaxf(C1 * Fv[jj], C2 * Hv[jj]);   // exact lrelu-exp
                    const bool on = (mk[jj] != 0) || (jj0 + jj == i);
                    p[jj] = on ? sel : 0.f;
                    ls += p[jj];
                }
                lacc[rr] += ls;
                uint4 st;
                __half2 h;
                h = __floats2half2_rn(p[0], p[1]); st.x = *(uint32_t*)&h;
                h = __floats2half2_rn(p[2], p[3]); st.y = *(uint32_t*)&h;
                h = __floats2half2_rn(p[4], p[5]); st.z = *(uint32_t*)&h;
                h = __floats2half2_rn(p[6], p[7]); st.w = *(uint32_t*)&h;
                *(uint4*)(Pt + row * PSTR + jq * 8) = st;
            }
        }
        CP_WAIT0();                       // B(t) landed (own chunks)
        __syncthreads();                  // P(t),B(t) visible; adjS consumed; MMA(t-1) done
        // ---- refill adj(t+1) + B(t+1) (overlap MMA(t)) ----
        if (t + 1 < NT) {
            if (tid == 0) MBARRIER_EXPECT_TX(mb, 65536);
            if (tid < 128)
                BULK_G2S(adj_u + (uint32_t)tid * (ADJSTR * 4),
                         (const void*)(adj + (size_t)(i0 + tid) * NN + jbase + (t + 1) * 128),
                         512, mb);
            const char* bs2 = (const char*)(bsrc0 + (t + 1) * 128);
            const uint32_t bd = bs_u + ((t + 1) & 1) * PTILE + bhalf;
#pragma unroll
            for (int it = 0; it < 8; it++) CP_ASYNC16(bd + it * 16, bs2 + it * 16);
            CP_COMMIT();
        }
        // ---- MMA(t) ----
        {
            const uint32_t pb = ps_u + s * PTILE;
            const uint32_t bb = bs_u + s * PTILE;
            const int m0r = wm * 32, n0 = wn * 64;
#pragma unroll
            for (int ks = 0; ks < 8; ks++) {
                uint32_t a[2][4];
#pragma unroll
                for (int mt = 0; mt < 2; mt++) {
                    const uint32_t addr = pb + 2 * ((m0r + mt * 16 + (lane & 15)) * PSTR
                                                    + ks * 16 + (lane >> 4) * 8);
                    LDSM4(a[mt], addr);
                }
#pragma unroll
                for (int nt = 0; nt < 4; nt++) {
                    uint32_t bf[4];
                    const uint32_t addr = bb + 2 * ((n0 + nt * 16 + (lane & 7) + ((lane >> 4) << 3)) * PSTR
                                                    + ks * 16 + ((lane >> 3) & 1) * 8);
                    LDSM4(bf, addr);
#pragma unroll
                    for (int mt = 0; mt < 2; mt++) {
                        MMA16816(acc[mt][nt * 2 + 0], a[mt], bf[0], bf[1]);
                        MMA16816(acc[mt][nt * 2 + 1], a[mt], bf[2], bf[3]);
                    }
                }
            }
        }
        // no trailing sync: next iter's build writes the OTHER P buffer;
        // cross-warp safety comes from the single mid-loop __syncthreads.
    }

    // ---- epilogue ----
    {
        float* dst = g_part + ((size_t)js * NN + i0) * FOUT;
        const int rbase = wm * 32 + (lane >> 2);
        const int cbase = wn * 64 + (lane & 3) * 2;
#pragma unroll
        for (int mt = 0; mt < 2; mt++) {
#pragma unroll
            for (int nf = 0; nf < 8; nf++) {
                const int r = rbase + mt * 16;
                const int c = cbase + nf * 8;
                *(float2*)(dst + (size_t)r * FOUT + c) =
                    make_float2(acc[mt][nf][0], acc[mt][nf][1]);
                *(float2*)(dst + (size_t)(r + 8) * FOUT + c) =
                    make_float2(acc[mt][nf][2], acc[mt][nf][3]);
            }
        }
    }
    __syncthreads();                      // all MMA/ldsm done before aliasing P
    float* s_l = (float*)(smem + SM_P);
#pragma unroll
    for (int rr = 0; rr < 8; rr++) s_l[(rq * 8 + rr) * 16 + jq] = lacc[rr];
    __syncthreads();
    if (tid < 128) {
        float L = 0.f;
#pragma unroll
        for (int q = 0; q < 16; q++) L += s_l[tid * 16 + q];
        g_lpart[js * NN + i0 + tid] = L;
    }
}

// ================= Kernel 5: combine + sigmoid =================
__global__ void combine_kernel(float* __restrict__ out) {
    const int gid = blockIdx.x * 256 + threadIdx.x;
    const int i = gid >> 5;
    const int c = gid & 31;
    float4 s = make_float4(0.f, 0.f, 0.f, 0.f);
    float L = 0.f;
#pragma unroll
    for (int js = 0; js < JS; js++) {
        const float4 a = *(const float4*)(g_part + ((size_t)js * NN + i) * FOUT + c * 4);
        s.x += a.x; s.y += a.y; s.z += a.z; s.w += a.w;
        L += g_lpart[js * NN + i];
    }
    const float inv = 1.f / L;
    float4 o;
    o.x = 1.f / (1.f + __expf(-s.x * inv));
    o.y = 1.f / (1.f + __expf(-s.y * inv));
    o.z = 1.f / (1.f + __expf(-s.z * inv));
    o.w = 1.f / (1.f + __expf(-s.w * inv));
    *(float4*)(out + (size_t)i * FOUT + c * 4) = o;
}

extern "C" void kernel_launch(void* const* d_in, const int* in_sizes, int n_in,
                              void* d_out, int out_size) {
    const float* X   = (const float*)d_in[0];
    const int*   adj = (const int*)  d_in[1];
    const float* W   = (const float*)d_in[2];
    const float* b   = (const float*)d_in[3];
    const float* S   = (const float*)d_in[4];
    float* out = (float*)d_out;

    gemm_xp_kernel<<<dim3(FOUT / 64, NN / 64), dim3(16, 16)>>>(X, W, b);
    proj_kernel<<<(NN * 32) / 256, 256>>>(S);
    maxred_kernel<<<1, 1024>>>();

    cudaFuncSetAttribute(attn_kernel, cudaFuncAttributeMaxDynamicSharedMemorySize, SMEM_ATTN);
    attn_kernel<<<dim3(NN / 128, JS), 256, SMEM_ATTN>>>(adj);
    combine_kernel<<<(NN * 32) / 256, 256>>>(out);
}